// round 1
// baseline (speedup 1.0000x reference)
#include <cuda_runtime.h>
#include <math.h>

#define NQ    1024
#define FEWS  5
#define MCAND 200
#define KSEL  32
#define DD    128
#define DMM   256
#define DFF   512
#define HHH   512
#define G4    2048
#define RTOT  (NQ + FEWS)   // 1029

// ---------------- workspace (device globals; no allocations) ----------------
__device__ float g_cat  [RTOT * DMM];   // [query_neighbor ; support_neighbor]
__device__ float g_h1   [RTOT * DFF];
__device__ float g_h2   [RTOT * DMM];
__device__ float g_qg   [NQ   * DMM];   // query_g
__device__ float g_sse  [FEWS * DMM];   // SE(support rows)
__device__ float g_sg   [DMM];          // support_g
__device__ float g_sgn  [DMM];          // l2norm(support_g)
__device__ float g_bsum [G4];           // b_ih + b_hh
__device__ float g_Gx   [NQ * G4];
__device__ float g_gates[NQ * G4];
__device__ float g_c0   [NQ * HHH];
__device__ float g_hr   [NQ * HHH];

// ---------------- neighbor encoder: one block per row ----------------
__global__ __launch_bounds__(256)
void neighbor_kernel(const float* __restrict__ emb,
                     const int*   __restrict__ conn,   // (R, M, 2)
                     const int*   __restrict__ ids,    // (R, 2)
                     int col,
                     const float* __restrict__ gcnW,   // (128, 256)
                     const float* __restrict__ gbias,
                     const float* __restrict__ gb,
                     int row_base, int col_off)
{
    const int row  = blockIdx.x;
    const int t    = threadIdx.x;
    const int lane = t & 31;
    const int w    = t >> 5;

    __shared__ __align__(16) float s_center[DD];
    __shared__ float s_sim [MCAND];
    __shared__ int   s_ridx[MCAND];
    __shared__ int   s_eidx[MCAND];
    __shared__ int   s_flag[MCAND];
    __shared__ float s_mcat[DMM];
    __shared__ float s_red[8];
    __shared__ float s_cn;

    for (int n = t; n < MCAND; n += 256) {
        s_ridx[n] = conn[((size_t)row * MCAND + n) * 2 + 0];
        s_eidx[n] = conn[((size_t)row * MCAND + n) * 2 + 1];
    }
    const int cid = ids[row * 2 + col];
    float cv = 0.f;
    if (t < DD) { cv = emb[(size_t)cid * DD + t]; s_center[t] = cv; }

    // center norm (block reduce)
    float p = cv * cv;
    #pragma unroll
    for (int o = 16; o; o >>= 1) p += __shfl_down_sync(0xffffffffu, p, o);
    if (lane == 0) s_red[w] = p;
    __syncthreads();
    if (t == 0) {
        float s = 0.f;
        #pragma unroll
        for (int i = 0; i < 8; i++) s += s_red[i];
        s_cn = sqrtf(s);
    }
    __syncthreads();
    const float cn = s_cn;

    // cosine similarities: warp per neighbor (float4 per lane = 128 floats)
    const float4 c4 = *(const float4*)(s_center + lane * 4);
    for (int n = w; n < MCAND; n += 8) {
        const float4 e4 = *(const float4*)(emb + (size_t)s_eidx[n] * DD + lane * 4);
        float num = e4.x*c4.x + e4.y*c4.y + e4.z*c4.z + e4.w*c4.w;
        float nn  = e4.x*e4.x + e4.y*e4.y + e4.z*e4.z + e4.w*e4.w;
        #pragma unroll
        for (int o = 16; o; o >>= 1) {
            num += __shfl_down_sync(0xffffffffu, num, o);
            nn  += __shfl_down_sync(0xffffffffu, nn,  o);
        }
        if (lane == 0) {
            float den = fmaxf(cn * sqrtf(nn), 1e-8f);
            s_sim[n] = num / den;
        }
    }
    __syncthreads();

    // top-K selection with jax.lax.top_k tie-break (lower index wins)
    if (t < MCAND) {
        const float v = s_sim[t];
        int r = 0;
        for (int i = 0; i < MCAND; i++) {
            const float u = s_sim[i];
            r += (u > v) || (u == v && i < t);
        }
        s_flag[t] = (r < KSEL) ? 1 : 0;
    }
    __syncthreads();

    // deterministic-order mean of selected [rel ; ent]
    {
        float acc = 0.f;
        if (t < DD) {
            for (int n = 0; n < MCAND; n++)
                if (s_flag[n]) acc += emb[(size_t)s_ridx[n] * DD + t];
        } else {
            const int d = t - DD;
            for (int n = 0; n < MCAND; n++)
                if (s_flag[n]) acc += emb[(size_t)s_eidx[n] * DD + d];
        }
        s_mcat[t] = acc * (1.f / KSEL);
    }
    __syncthreads();

    // GEMV 256 -> 128 (+ biases, tanh); warp w does 16 outputs, coalesced W reads
    for (int dd = 0; dd < 16; dd++) {
        const int d = w * 16 + dd;
        const float* wr = gcnW + (size_t)d * DMM;
        float pp = 0.f;
        #pragma unroll
        for (int c = lane; c < DMM; c += 32) pp += wr[c] * s_mcat[c];
        #pragma unroll
        for (int o = 16; o; o >>= 1) pp += __shfl_down_sync(0xffffffffu, pp, o);
        if (lane == 0)
            g_cat[(size_t)(row_base + row) * DMM + col_off + d] =
                tanhf(pp + gbias[d] + gb[d]);
    }
}

// ---------------- tiled SGEMM: C[M,N] = A[M,K] @ B[N,K]^T (+epilogue) ----------------
// EPI: 0 = +bias[n], 1 = relu(+bias[n]), 2 = +Cadd[m,n]
template <int EPI>
__global__ __launch_bounds__(256)
void sgemm_nt(const float* __restrict__ A, const float* __restrict__ Bm,
              float* __restrict__ C, int M, int N, int K,
              const float* __restrict__ bias, const float* __restrict__ Cadd)
{
    __shared__ __align__(16) float As[16][64];
    __shared__ __align__(16) float Bs[16][64];
    const int tx = threadIdx.x & 15;
    const int ty = threadIdx.x >> 4;
    const int m0 = blockIdx.y * 64;
    const int n0 = blockIdx.x * 64;

    float acc[4][4] = {{0.f}};

    for (int k0 = 0; k0 < K; k0 += 16) {
        for (int l = threadIdx.x; l < 1024; l += 256) {
            const int mm = l >> 4, kk = l & 15;
            const int m = m0 + mm;
            As[kk][mm] = (m < M) ? A[(size_t)m * K + k0 + kk] : 0.f;
            Bs[kk][mm] = Bm[(size_t)(n0 + mm) * K + k0 + kk];
        }
        __syncthreads();
        #pragma unroll
        for (int kk = 0; kk < 16; kk++) {
            const float4 a4 = *(const float4*)&As[kk][ty * 4];
            const float4 b4 = *(const float4*)&Bs[kk][tx * 4];
            const float av[4] = {a4.x, a4.y, a4.z, a4.w};
            const float bv[4] = {b4.x, b4.y, b4.z, b4.w};
            #pragma unroll
            for (int i = 0; i < 4; i++)
                #pragma unroll
                for (int j = 0; j < 4; j++)
                    acc[i][j] += av[i] * bv[j];
        }
        __syncthreads();
    }

    #pragma unroll
    for (int i = 0; i < 4; i++) {
        const int m = m0 + ty * 4 + i;
        if (m < M) {
            #pragma unroll
            for (int j = 0; j < 4; j++) {
                const int n = n0 + tx * 4 + j;
                float v = acc[i][j];
                if (EPI == 0)      v += bias[n];
                else if (EPI == 1) v = fmaxf(v + bias[n], 0.f);
                else               v += Cadd[(size_t)m * N + n];
                C[(size_t)m * N + n] = v;
            }
        }
    }
}

// ---------------- residual + layernorm ----------------
__global__ __launch_bounds__(256)
void ln_kernel(const float* __restrict__ g, const float* __restrict__ b)
{
    const int row = blockIdx.x;
    const int t = threadIdx.x;
    const int lane = t & 31, w = t >> 5;
    const float x = g_cat[(size_t)row * DMM + t];
    const float y = g_h2[(size_t)row * DMM + t] + x;

    __shared__ float s1[8], s2[8];
    __shared__ float s_mu, s_rs;
    float s = y, ss = y * y;
    #pragma unroll
    for (int o = 16; o; o >>= 1) {
        s  += __shfl_down_sync(0xffffffffu, s,  o);
        ss += __shfl_down_sync(0xffffffffu, ss, o);
    }
    if (lane == 0) { s1[w] = s; s2[w] = ss; }
    __syncthreads();
    if (t == 0) {
        float S = 0.f, SS = 0.f;
        #pragma unroll
        for (int i = 0; i < 8; i++) { S += s1[i]; SS += s2[i]; }
        const float mu = S / DMM;
        const float var = SS / DMM - mu * mu;
        s_mu = mu; s_rs = rsqrtf(var + 1e-5f);
    }
    __syncthreads();
    const float o = g[t] * (y - s_mu) * s_rs + b[t];
    if (row < NQ) g_qg[(size_t)row * DMM + t] = o;
    else          g_sse[(size_t)(row - NQ) * DMM + t] = o;
}

// ---------------- support mean + l2norm ----------------
__global__ __launch_bounds__(256)
void support_reduce()
{
    const int t = threadIdx.x;
    const int lane = t & 31, w = t >> 5;
    float s = 0.f;
    #pragma unroll
    for (int r = 0; r < FEWS; r++) s += g_sse[r * DMM + t];
    s *= (1.f / FEWS);
    g_sg[t] = s;

    __shared__ float s1[8];
    __shared__ float s_n;
    float p = s * s;
    #pragma unroll
    for (int o = 16; o; o >>= 1) p += __shfl_down_sync(0xffffffffu, p, o);
    if (lane == 0) s1[w] = p;
    __syncthreads();
    if (t == 0) {
        float S = 0.f;
        #pragma unroll
        for (int i = 0; i < 8; i++) S += s1[i];
        s_n = fmaxf(sqrtf(S), 1e-12f);
    }
    __syncthreads();
    g_sgn[t] = s / s_n;
}

// ---------------- bias fold ----------------
__global__ void bias_sum(const float* __restrict__ bih, const float* __restrict__ bhh)
{
    const int i = blockIdx.x * 256 + threadIdx.x;
    if (i < G4) g_bsum[i] = bih[i] + bhh[i];
}

// ---------------- LSTM step 0 (h_r = 0 => gates = Gx; attn==1 => r = support_g) ----------------
__global__ __launch_bounds__(256)
void e0_kernel()
{
    const int idx = blockIdx.x * 256 + threadIdx.x;
    if (idx >= NQ * HHH) return;
    const int row = idx / HHH, j = idx % HHH;
    const float* gr = g_Gx + (size_t)row * G4;
    const float ig = 1.f / (1.f + expf(-gr[j]));
    const float gg = tanhf(gr[1024 + j]);
    const float c  = ig * gg;                       // f * c_prev term is zero
    g_c0[idx] = c;
    const float og = 1.f / (1.f + expf(-gr[1536 + j]));
    const float hf = og * tanhf(c);
    if (j < DMM) g_hr[(size_t)row * HHH + j] = g_qg[(size_t)row * DMM + j] + hf;
    else         g_hr[(size_t)row * HHH + j] = g_sg[j - DMM];
}

// ---------------- LSTM step 1 + l2norm + final dot ----------------
__global__ __launch_bounds__(256)
void final_kernel(float* __restrict__ out)
{
    const int row = blockIdx.x;
    const int t = threadIdx.x;
    const int lane = t & 31, w = t >> 5;
    const float* gr = g_gates + (size_t)row * G4;
    const float ig = 1.f / (1.f + expf(-gr[t]));
    const float fg = 1.f / (1.f + expf(-gr[512 + t]));
    const float gg = tanhf(gr[1024 + t]);
    const float og = 1.f / (1.f + expf(-gr[1536 + t]));
    const float c  = fg * g_c0[(size_t)row * HHH + t] + ig * gg;
    const float h  = g_qg[(size_t)row * DMM + t] + og * tanhf(c);

    float d = h * g_sgn[t];
    float n2 = h * h;
    __shared__ float sd[8], sn[8];
    #pragma unroll
    for (int o = 16; o; o >>= 1) {
        d  += __shfl_down_sync(0xffffffffu, d,  o);
        n2 += __shfl_down_sync(0xffffffffu, n2, o);
    }
    if (lane == 0) { sd[w] = d; sn[w] = n2; }
    __syncthreads();
    if (t == 0) {
        float DT = 0.f, NT = 0.f;
        #pragma unroll
        for (int i = 0; i < 8; i++) { DT += sd[i]; NT += sn[i]; }
        out[row] = DT / fmaxf(sqrtf(NT), 1e-12f);
    }
}

// ---------------- launch ----------------
extern "C" void kernel_launch(void* const* d_in, const int* in_sizes, int n_in,
                              void* d_out, int out_size)
{
    const int*   query   = (const int*)  d_in[0];
    const int*   support = (const int*)  d_in[1];
    const int*   qlc     = (const int*)  d_in[2];
    const int*   qrc     = (const int*)  d_in[4];
    const int*   slc     = (const int*)  d_in[6];
    const int*   src     = (const int*)  d_in[8];
    const float* emb     = (const float*)d_in[10];
    const float* gcnW    = (const float*)d_in[11];
    const float* gbias   = (const float*)d_in[12];
    const float* gb      = (const float*)d_in[13];
    const float* w1      = (const float*)d_in[14];
    const float* b1      = (const float*)d_in[15];
    const float* w2      = (const float*)d_in[16];
    const float* b2      = (const float*)d_in[17];
    const float* lng     = (const float*)d_in[18];
    const float* lnb     = (const float*)d_in[19];
    const float* Wih     = (const float*)d_in[20];
    const float* Whh     = (const float*)d_in[21];
    const float* bih     = (const float*)d_in[22];
    const float* bhh     = (const float*)d_in[23];
    float* out = (float*)d_out;

    float *p_cat, *p_h1, *p_h2, *p_qg, *p_bsum, *p_Gx, *p_gates, *p_hr;
    cudaGetSymbolAddress((void**)&p_cat,   g_cat);
    cudaGetSymbolAddress((void**)&p_h1,    g_h1);
    cudaGetSymbolAddress((void**)&p_h2,    g_h2);
    cudaGetSymbolAddress((void**)&p_qg,    g_qg);
    cudaGetSymbolAddress((void**)&p_bsum,  g_bsum);
    cudaGetSymbolAddress((void**)&p_Gx,    g_Gx);
    cudaGetSymbolAddress((void**)&p_gates, g_gates);
    cudaGetSymbolAddress((void**)&p_hr,    g_hr);

    bias_sum<<<8, 256>>>(bih, bhh);

    neighbor_kernel<<<NQ,   256>>>(emb, qlc, query,   0, gcnW, gbias, gb, 0,  0);
    neighbor_kernel<<<NQ,   256>>>(emb, qrc, query,   1, gcnW, gbias, gb, 0,  DD);
    neighbor_kernel<<<FEWS, 256>>>(emb, slc, support, 0, gcnW, gbias, gb, NQ, 0);
    neighbor_kernel<<<FEWS, 256>>>(emb, src, support, 1, gcnW, gbias, gb, NQ, DD);

    // support encoder (query + support rows batched): h1 = relu(x@w1^T+b1); h2 = h1@w2^T+b2
    sgemm_nt<1><<<dim3(DFF / 64, (RTOT + 63) / 64), 256>>>(p_cat, w1, p_h1, RTOT, DFF, DMM, b1, nullptr);
    sgemm_nt<0><<<dim3(DMM / 64, (RTOT + 63) / 64), 256>>>(p_h1, w2, p_h2, RTOT, DMM, DFF, b2, nullptr);
    ln_kernel<<<RTOT, 256>>>(lng, lnb);
    support_reduce<<<1, 256>>>();

    // query encoder
    sgemm_nt<0><<<dim3(G4 / 64, NQ / 64), 256>>>(p_qg, Wih, p_Gx, NQ, G4, DMM, p_bsum, nullptr);
    e0_kernel<<<(NQ * HHH) / 256, 256>>>();
    sgemm_nt<2><<<dim3(G4 / 64, NQ / 64), 256>>>(p_hr, Whh, p_gates, NQ, G4, HHH, nullptr, p_Gx);
    final_kernel<<<NQ, 256>>>(out);
}

// round 2
// speedup vs baseline: 1.8014x; 1.8014x over previous
#include <cuda_runtime.h>
#include <math.h>

#define NQ    1024
#define FEWS  5
#define MCAND 200
#define KSEL  32
#define DD    128
#define DMM   256
#define DFF   512
#define HHH   512
#define GC    1024            // compacted gate columns (4 x 256)
#define RTOT  (NQ + FEWS)     // 1029
#define NBLK  (2*NQ + 2*FEWS) // 2058 neighbor tasks

// ---------------- workspace (device globals; no allocations) ----------------
__device__ float g_cat  [RTOT * DMM];
__device__ float g_h1   [RTOT * DFF];
__device__ float g_h2   [RTOT * DMM];
__device__ float g_qg   [NQ   * DMM];
__device__ float g_sse  [FEWS * DMM];
__device__ float g_sg   [DMM];
__device__ float g_sgn  [DMM];
__device__ float g_WihC [GC * DMM];
__device__ float g_WhhC [GC * DMM];
__device__ float g_bsumC[GC];
__device__ float g_svec [GC];
__device__ float g_GxC  [NQ * GC];
__device__ float g_gates[NQ * GC];
__device__ float g_c0   [NQ * DMM];
__device__ float g_hr   [NQ * DMM];

__device__ __forceinline__ int orig_col(int r) { return ((r >> 8) << 9) + (r & 255); }

// ---------------- weight compaction: live gate columns only ----------------
__global__ __launch_bounds__(256)
void compact_kernel(const float* __restrict__ Wih, const float* __restrict__ Whh,
                    const float* __restrict__ bih, const float* __restrict__ bhh)
{
    const int idx = blockIdx.x * 256 + threadIdx.x;   // GC*DMM threads
    const int r = idx >> 8, c = idx & 255;
    const int o = orig_col(r);
    g_WihC[idx] = Wih[(size_t)o * DMM + c];
    g_WhhC[idx] = Whh[(size_t)o * HHH + c];
    if (c == 0) g_bsumC[r] = bih[o] + bhh[o];
}

// ---------------- svec[r] = dot(Whh[orig(r), 256:512], support_g) ----------------
__global__ __launch_bounds__(256)
void svec_kernel(const float* __restrict__ Whh)
{
    const int lane = threadIdx.x & 31;
    const int r = blockIdx.x * 8 + (threadIdx.x >> 5);   // grid 128 -> 1024 warps
    const int o = orig_col(r);
    const float* wr = Whh + (size_t)o * HHH + DMM;
    float p = 0.f;
    #pragma unroll
    for (int c = lane; c < DMM; c += 32) p += wr[c] * g_sg[c];
    #pragma unroll
    for (int off = 16; off; off >>= 1) p += __shfl_down_sync(0xffffffffu, p, off);
    if (lane == 0) g_svec[r] = p;
}

// ---------------- neighbor encoder: all 2058 tasks in one launch ----------------
__global__ __launch_bounds__(256)
void neighbor_all(const float* __restrict__ emb,
                  const int* __restrict__ qlc, const int* __restrict__ qrc,
                  const int* __restrict__ slc, const int* __restrict__ src,
                  const int* __restrict__ query, const int* __restrict__ support,
                  const float* __restrict__ gcnW,
                  const float* __restrict__ gbias, const float* __restrict__ gb)
{
    const int b = blockIdx.x;
    const int t = threadIdx.x;
    const int lane = t & 31;
    const int w = t >> 5;

    const int* conn_row;
    int cid, out_row, coff;
    if (b < NQ)            { conn_row = qlc + (size_t)b * MCAND * 2;            cid = query[b * 2 + 0];           out_row = b;                 coff = 0;  }
    else if (b < 2 * NQ)   { int rb = b - NQ;   conn_row = qrc + (size_t)rb * MCAND * 2; cid = query[rb * 2 + 1]; out_row = rb;                coff = DD; }
    else if (b < 2*NQ+FEWS){ int rb = b - 2*NQ; conn_row = slc + (size_t)rb * MCAND * 2; cid = support[rb*2 + 0]; out_row = NQ + rb;           coff = 0;  }
    else                   { int rb = b - 2*NQ - FEWS; conn_row = src + (size_t)rb * MCAND * 2; cid = support[rb*2 + 1]; out_row = NQ + rb;    coff = DD; }

    __shared__ __align__(16) float s_center[DD];
    __shared__ float s_sim [MCAND];
    __shared__ int   s_ridx[MCAND];
    __shared__ int   s_eidx[MCAND];
    __shared__ int   s_selr[KSEL];
    __shared__ int   s_sele[KSEL];
    __shared__ float s_mcat[DMM];
    __shared__ float s_red[8];
    __shared__ float s_cn;

    for (int n = t; n < MCAND; n += 256) {
        s_ridx[n] = conn_row[n * 2 + 0];
        s_eidx[n] = conn_row[n * 2 + 1];
    }
    float cv = 0.f;
    if (t < DD) { cv = emb[(size_t)cid * DD + t]; s_center[t] = cv; }

    float p = cv * cv;
    #pragma unroll
    for (int o = 16; o; o >>= 1) p += __shfl_down_sync(0xffffffffu, p, o);
    if (lane == 0) s_red[w] = p;
    __syncthreads();
    if (t == 0) {
        float s = 0.f;
        #pragma unroll
        for (int i = 0; i < 8; i++) s += s_red[i];
        s_cn = sqrtf(s);
    }
    __syncthreads();
    const float cn = s_cn;

    // cosine sims: warp per neighbor
    const float4 c4 = *(const float4*)(s_center + lane * 4);
    for (int n = w; n < MCAND; n += 8) {
        const float4 e4 = *(const float4*)(emb + (size_t)s_eidx[n] * DD + lane * 4);
        float num = e4.x*c4.x + e4.y*c4.y + e4.z*c4.z + e4.w*c4.w;
        float nn  = e4.x*e4.x + e4.y*e4.y + e4.z*e4.z + e4.w*e4.w;
        #pragma unroll
        for (int o = 16; o; o >>= 1) {
            num += __shfl_down_sync(0xffffffffu, num, o);
            nn  += __shfl_down_sync(0xffffffffu, nn,  o);
        }
        if (lane == 0) {
            float den = fmaxf(cn * sqrtf(nn), 1e-8f);
            s_sim[n] = num / den;
        }
    }
    __syncthreads();

    // top-K with jax.lax.top_k tie-break (lower index wins); rank is a permutation
    if (t < MCAND) {
        const float v = s_sim[t];
        int r = 0;
        for (int i = 0; i < MCAND; i++) {
            const float u = s_sim[i];
            r += (u > v) || (u == v && i < t);
        }
        if (r < KSEL) { s_selr[r] = s_ridx[t]; s_sele[r] = s_eidx[t]; }
    }
    __syncthreads();

    // mean of selected [rel ; ent] via compacted list (coalesced rows, high MLP)
    {
        float acc = 0.f;
        if (t < DD) {
            #pragma unroll 8
            for (int k = 0; k < KSEL; k++) acc += emb[(size_t)s_selr[k] * DD + t];
        } else {
            const int d = t - DD;
            #pragma unroll 8
            for (int k = 0; k < KSEL; k++) acc += emb[(size_t)s_sele[k] * DD + d];
        }
        s_mcat[t] = acc * (1.f / KSEL);
    }
    __syncthreads();

    // GEMV 256 -> 128 (+biases, tanh)
    for (int dd = 0; dd < 16; dd++) {
        const int d = w * 16 + dd;
        const float* wr = gcnW + (size_t)d * DMM;
        float pp = 0.f;
        #pragma unroll
        for (int c = lane; c < DMM; c += 32) pp += wr[c] * s_mcat[c];
        #pragma unroll
        for (int o = 16; o; o >>= 1) pp += __shfl_down_sync(0xffffffffu, pp, o);
        if (lane == 0)
            g_cat[(size_t)out_row * DMM + coff + d] = tanhf(pp + gbias[d] + gb[d]);
    }
}

// ---------------- SGEMM: C[M,N] = A[M,K] @ B[N,K]^T (+epilogue) ----------------
// tile 128x64, BK=8, 256 threads, 8x4 per thread
// EPI: 0 = +bias[n], 1 = relu(+bias[n]), 2 = +Cadd[m,n] + bias[n]
template <int EPI>
__global__ __launch_bounds__(256)
void sgemm_nt(const float* __restrict__ A, const float* __restrict__ Bm,
              float* __restrict__ C, int M, int N, int K,
              const float* __restrict__ bias, const float* __restrict__ Cadd)
{
    __shared__ __align__(16) float As[8][132];
    __shared__ __align__(16) float Bs[8][68];
    const int t = threadIdx.x;
    const int m0 = blockIdx.y * 128;
    const int n0 = blockIdx.x * 64;
    const int w = t >> 5, lane = t & 31;
    const int wm = w & 1, wn = w >> 1;
    const int lm = lane & 7, ln = lane >> 3;
    const int mBase = wm * 64 + lm * 8;
    const int nBase = wn * 16 + ln * 4;

    const int aRow = t >> 1;
    const int aK   = (t & 1) * 4;

    float acc[8][4] = {{0.f}};

    for (int k0 = 0; k0 < K; k0 += 8) {
        float4 av = make_float4(0.f, 0.f, 0.f, 0.f);
        const int m = m0 + aRow;
        if (m < M) av = *(const float4*)(A + (size_t)m * K + k0 + aK);
        As[aK+0][aRow] = av.x; As[aK+1][aRow] = av.y;
        As[aK+2][aRow] = av.z; As[aK+3][aRow] = av.w;
        if (t < 128) {
            const float4 bv = *(const float4*)(Bm + (size_t)(n0 + aRow) * K + k0 + aK);
            Bs[aK+0][aRow] = bv.x; Bs[aK+1][aRow] = bv.y;
            Bs[aK+2][aRow] = bv.z; Bs[aK+3][aRow] = bv.w;
        }
        __syncthreads();
        #pragma unroll
        for (int k = 0; k < 8; k++) {
            const float4 a0 = *(const float4*)&As[k][mBase];
            const float4 a1 = *(const float4*)&As[k][mBase + 4];
            const float4 b0 = *(const float4*)&Bs[k][nBase];
            const float am[8] = {a0.x,a0.y,a0.z,a0.w,a1.x,a1.y,a1.z,a1.w};
            const float bn[4] = {b0.x,b0.y,b0.z,b0.w};
            #pragma unroll
            for (int i = 0; i < 8; i++)
                #pragma unroll
                for (int j = 0; j < 4; j++)
                    acc[i][j] += am[i] * bn[j];
        }
        __syncthreads();
    }

    const int nIdx = n0 + nBase;
    float4 bv4 = make_float4(0.f,0.f,0.f,0.f);
    if (EPI == 0 || EPI == 1 || EPI == 2) bv4 = *(const float4*)(bias + nIdx);
    #pragma unroll
    for (int i = 0; i < 8; i++) {
        const int m = m0 + mBase + i;
        if (m < M) {
            float4 v = make_float4(acc[i][0], acc[i][1], acc[i][2], acc[i][3]);
            v.x += bv4.x; v.y += bv4.y; v.z += bv4.z; v.w += bv4.w;
            if (EPI == 1) {
                v.x = fmaxf(v.x, 0.f); v.y = fmaxf(v.y, 0.f);
                v.z = fmaxf(v.z, 0.f); v.w = fmaxf(v.w, 0.f);
            } else if (EPI == 2) {
                const float4 cadd = *(const float4*)(Cadd + (size_t)m * N + nIdx);
                v.x += cadd.x; v.y += cadd.y; v.z += cadd.z; v.w += cadd.w;
            }
            *(float4*)(C + (size_t)m * N + nIdx) = v;
        }
    }
}

// ---------------- residual + layernorm ----------------
__global__ __launch_bounds__(256)
void ln_kernel(const float* __restrict__ g, const float* __restrict__ b)
{
    const int row = blockIdx.x;
    const int t = threadIdx.x;
    const int lane = t & 31, w = t >> 5;
    const float x = g_cat[(size_t)row * DMM + t];
    const float y = g_h2[(size_t)row * DMM + t] + x;

    __shared__ float s1[8], s2[8];
    __shared__ float s_mu, s_rs;
    float s = y, ss = y * y;
    #pragma unroll
    for (int o = 16; o; o >>= 1) {
        s  += __shfl_down_sync(0xffffffffu, s,  o);
        ss += __shfl_down_sync(0xffffffffu, ss, o);
    }
    if (lane == 0) { s1[w] = s; s2[w] = ss; }
    __syncthreads();
    if (t == 0) {
        float S = 0.f, SS = 0.f;
        #pragma unroll
        for (int i = 0; i < 8; i++) { S += s1[i]; SS += s2[i]; }
        const float mu = S / DMM;
        const float var = SS / DMM - mu * mu;
        s_mu = mu; s_rs = rsqrtf(var + 1e-5f);
    }
    __syncthreads();
    const float o = g[t] * (y - s_mu) * s_rs + b[t];
    if (row < NQ) g_qg[(size_t)row * DMM + t] = o;
    else          g_sse[(size_t)(row - NQ) * DMM + t] = o;
}

// ---------------- support mean + l2norm ----------------
__global__ __launch_bounds__(256)
void support_reduce()
{
    const int t = threadIdx.x;
    const int lane = t & 31, w = t >> 5;
    float s = 0.f;
    #pragma unroll
    for (int r = 0; r < FEWS; r++) s += g_sse[r * DMM + t];
    s *= (1.f / FEWS);
    g_sg[t] = s;

    __shared__ float s1[8];
    __shared__ float s_n;
    float p = s * s;
    #pragma unroll
    for (int o = 16; o; o >>= 1) p += __shfl_down_sync(0xffffffffu, p, o);
    if (lane == 0) s1[w] = p;
    __syncthreads();
    if (t == 0) {
        float S = 0.f;
        #pragma unroll
        for (int i = 0; i < 8; i++) S += s1[i];
        s_n = fmaxf(sqrtf(S), 1e-12f);
    }
    __syncthreads();
    g_sgn[t] = s / s_n;
}

// ---------------- LSTM step 0 on compacted gates ----------------
__global__ __launch_bounds__(256)
void e0_kernel()
{
    const int idx = blockIdx.x * 256 + threadIdx.x;   // NQ*256
    const int row = idx >> 8, j = idx & 255;
    const float* gr = g_GxC + (size_t)row * GC;
    const float ig = 1.f / (1.f + expf(-gr[j]));
    const float gg = tanhf(gr[512 + j]);
    const float c  = ig * gg;
    g_c0[idx] = c;
    const float og = 1.f / (1.f + expf(-gr[768 + j]));
    g_hr[idx] = g_qg[idx] + og * tanhf(c);
}

// ---------------- LSTM step 1 + l2norm + final dot ----------------
__global__ __launch_bounds__(256)
void final_kernel(float* __restrict__ out)
{
    const int row = blockIdx.x;
    const int t = threadIdx.x;
    const int lane = t & 31, w = t >> 5;
    const float* gr = g_gates + (size_t)row * GC;
    const float ig = 1.f / (1.f + expf(-gr[t]));
    const float fg = 1.f / (1.f + expf(-gr[256 + t]));
    const float gg = tanhf(gr[512 + t]);
    const float og = 1.f / (1.f + expf(-gr[768 + t]));
    const float c  = fg * g_c0[(size_t)row * DMM + t] + ig * gg;
    const float h  = g_qg[(size_t)row * DMM + t] + og * tanhf(c);

    float d = h * g_sgn[t];
    float n2 = h * h;
    __shared__ float sd[8], sn[8];
    #pragma unroll
    for (int o = 16; o; o >>= 1) {
        d  += __shfl_down_sync(0xffffffffu, d,  o);
        n2 += __shfl_down_sync(0xffffffffu, n2, o);
    }
    if (lane == 0) { sd[w] = d; sn[w] = n2; }
    __syncthreads();
    if (t == 0) {
        float DT = 0.f, NT = 0.f;
        #pragma unroll
        for (int i = 0; i < 8; i++) { DT += sd[i]; NT += sn[i]; }
        out[row] = DT / fmaxf(sqrtf(NT), 1e-12f);
    }
}

// ---------------- launch ----------------
extern "C" void kernel_launch(void* const* d_in, const int* in_sizes, int n_in,
                              void* d_out, int out_size)
{
    const int*   query   = (const int*)  d_in[0];
    const int*   support = (const int*)  d_in[1];
    const int*   qlc     = (const int*)  d_in[2];
    const int*   qrc     = (const int*)  d_in[4];
    const int*   slc     = (const int*)  d_in[6];
    const int*   src     = (const int*)  d_in[8];
    const float* emb     = (const float*)d_in[10];
    const float* gcnW    = (const float*)d_in[11];
    const float* gbias   = (const float*)d_in[12];
    const float* gb      = (const float*)d_in[13];
    const float* w1      = (const float*)d_in[14];
    const float* b1      = (const float*)d_in[15];
    const float* w2      = (const float*)d_in[16];
    const float* b2      = (const float*)d_in[17];
    const float* lng     = (const float*)d_in[18];
    const float* lnb     = (const float*)d_in[19];
    const float* Wih     = (const float*)d_in[20];
    const float* Whh     = (const float*)d_in[21];
    const float* bih     = (const float*)d_in[22];
    const float* bhh     = (const float*)d_in[23];
    float* out = (float*)d_out;

    float *p_cat, *p_h1, *p_h2, *p_qg, *p_WihC, *p_WhhC, *p_bsumC, *p_svec;
    float *p_GxC, *p_gates, *p_hr;
    cudaGetSymbolAddress((void**)&p_cat,   g_cat);
    cudaGetSymbolAddress((void**)&p_h1,    g_h1);
    cudaGetSymbolAddress((void**)&p_h2,    g_h2);
    cudaGetSymbolAddress((void**)&p_qg,    g_qg);
    cudaGetSymbolAddress((void**)&p_WihC,  g_WihC);
    cudaGetSymbolAddress((void**)&p_WhhC,  g_WhhC);
    cudaGetSymbolAddress((void**)&p_bsumC, g_bsumC);
    cudaGetSymbolAddress((void**)&p_svec,  g_svec);
    cudaGetSymbolAddress((void**)&p_GxC,   g_GxC);
    cudaGetSymbolAddress((void**)&p_gates, g_gates);
    cudaGetSymbolAddress((void**)&p_hr,    g_hr);

    compact_kernel<<<GC * DMM / 256, 256>>>(Wih, Whh, bih, bhh);
    neighbor_all<<<NBLK, 256>>>(emb, qlc, qrc, slc, src, query, support, gcnW, gbias, gb);

    // support encoder (batched query + support rows)
    sgemm_nt<1><<<dim3(DFF / 64, (RTOT + 127) / 128), 256>>>(p_cat, w1, p_h1, RTOT, DFF, DMM, b1, nullptr);
    sgemm_nt<0><<<dim3(DMM / 64, (RTOT + 127) / 128), 256>>>(p_h1, w2, p_h2, RTOT, DMM, DFF, b2, nullptr);
    ln_kernel<<<RTOT, 256>>>(lng, lnb);
    support_reduce<<<1, 256>>>();
    svec_kernel<<<GC / 8, 256>>>(Whh);

    // query encoder on compacted gate columns
    sgemm_nt<0><<<dim3(GC / 64, NQ / 128), 256>>>(p_qg, p_WihC, p_GxC, NQ, GC, DMM, p_bsumC, nullptr);
    e0_kernel<<<NQ * DMM / 256, 256>>>();
    sgemm_nt<2><<<dim3(GC / 64, NQ / 128), 256>>>(p_hr, p_WhhC, p_gates, NQ, GC, DMM, p_svec, p_GxC);
    final_kernel<<<NQ, 256>>>(out);
}

// round 3
// speedup vs baseline: 2.4746x; 1.3737x over previous
#include <cuda_runtime.h>
#include <math.h>

#define NQ    1024
#define FEWS  5
#define MCAND 200
#define KSEL  32
#define DD    128
#define DMM   256
#define DFF   512
#define HHH   512
#define GC    1024            // compacted gate columns (4 x 256)
#define RTOT  (NQ + FEWS)     // 1029
#define NBLK  (2*NQ + 2*FEWS) // 2058 neighbor tasks

// ---------------- workspace (device globals; no allocations) ----------------
__device__ float g_cat  [RTOT * DMM];
__device__ float g_h1   [RTOT * DFF];
__device__ float g_h2   [RTOT * DMM];
__device__ float g_qg   [NQ   * DMM];
__device__ float g_sse  [FEWS * DMM];
__device__ float g_sg   [DMM];
__device__ float g_sgn  [DMM];
__device__ float g_WihC [GC * DMM];
__device__ float g_WhhC [GC * DMM];
__device__ float g_bsumC[GC];
__device__ float g_svec [GC];
__device__ float g_GxC  [NQ * GC];
__device__ float g_gates[NQ * GC];
__device__ float g_c0   [NQ * DMM];
__device__ float g_hr   [NQ * DMM];

__device__ __forceinline__ int orig_col(int r) { return ((r >> 8) << 9) + (r & 255); }

// ---------------- weight compaction: live gate columns only ----------------
__global__ __launch_bounds__(256)
void compact_kernel(const float* __restrict__ Wih, const float* __restrict__ Whh,
                    const float* __restrict__ bih, const float* __restrict__ bhh)
{
    const int idx = blockIdx.x * 256 + threadIdx.x;   // GC*DMM threads
    const int r = idx >> 8, c = idx & 255;
    const int o = orig_col(r);
    g_WihC[idx] = Wih[(size_t)o * DMM + c];
    g_WhhC[idx] = Whh[(size_t)o * HHH + c];
    if (c == 0) g_bsumC[r] = bih[o] + bhh[o];
}

// ---------------- svec[r] = dot(Whh[orig(r), 256:512], support_g) ----------------
__global__ __launch_bounds__(256)
void svec_kernel(const float* __restrict__ Whh)
{
    const int lane = threadIdx.x & 31;
    const int r = blockIdx.x * 8 + (threadIdx.x >> 5);
    const int o = orig_col(r);
    const float* wr = Whh + (size_t)o * HHH + DMM;
    float p = 0.f;
    #pragma unroll
    for (int c = lane; c < DMM; c += 32) p += wr[c] * g_sg[c];
    #pragma unroll
    for (int off = 16; off; off >>= 1) p += __shfl_down_sync(0xffffffffu, p, off);
    if (lane == 0) g_svec[r] = p;
}

// ---------------- neighbor encoder: all 2058 tasks in one launch ----------------
__global__ __launch_bounds__(256)
void neighbor_all(const float* __restrict__ emb,
                  const int* __restrict__ qlc, const int* __restrict__ qrc,
                  const int* __restrict__ slc, const int* __restrict__ src,
                  const int* __restrict__ query, const int* __restrict__ support,
                  const float* __restrict__ gcnW,
                  const float* __restrict__ gbias, const float* __restrict__ gb)
{
    const int b = blockIdx.x;
    const int t = threadIdx.x;
    const int lane = t & 31;
    const int w = t >> 5;

    const int* conn_row;
    int cid, out_row, coff;
    if (b < NQ)            { conn_row = qlc + (size_t)b * MCAND * 2;            cid = query[b * 2 + 0];           out_row = b;                 coff = 0;  }
    else if (b < 2 * NQ)   { int rb = b - NQ;   conn_row = qrc + (size_t)rb * MCAND * 2; cid = query[rb * 2 + 1]; out_row = rb;                coff = DD; }
    else if (b < 2*NQ+FEWS){ int rb = b - 2*NQ; conn_row = slc + (size_t)rb * MCAND * 2; cid = support[rb*2 + 0]; out_row = NQ + rb;           coff = 0;  }
    else                   { int rb = b - 2*NQ - FEWS; conn_row = src + (size_t)rb * MCAND * 2; cid = support[rb*2 + 1]; out_row = NQ + rb;    coff = DD; }

    __shared__ __align__(16) float s_center[DD];
    __shared__ float s_sim [MCAND];
    __shared__ int   s_ridx[MCAND];
    __shared__ int   s_eidx[MCAND];
    __shared__ int   s_selr[KSEL];
    __shared__ int   s_sele[KSEL];
    __shared__ float s_mcat[DMM];
    __shared__ float s_red[8];
    __shared__ float s_cn;

    for (int n = t; n < MCAND; n += 256) {
        s_ridx[n] = conn_row[n * 2 + 0];
        s_eidx[n] = conn_row[n * 2 + 1];
    }
    float cv = 0.f;
    if (t < DD) { cv = emb[(size_t)cid * DD + t]; s_center[t] = cv; }

    float p = cv * cv;
    #pragma unroll
    for (int o = 16; o; o >>= 1) p += __shfl_down_sync(0xffffffffu, p, o);
    if (lane == 0) s_red[w] = p;
    __syncthreads();
    if (t == 0) {
        float s = 0.f;
        #pragma unroll
        for (int i = 0; i < 8; i++) s += s_red[i];
        s_cn = sqrtf(s);
    }
    __syncthreads();
    const float cn = s_cn;

    const float4 c4 = *(const float4*)(s_center + lane * 4);
    for (int n = w; n < MCAND; n += 8) {
        const float4 e4 = *(const float4*)(emb + (size_t)s_eidx[n] * DD + lane * 4);
        float num = e4.x*c4.x + e4.y*c4.y + e4.z*c4.z + e4.w*c4.w;
        float nn  = e4.x*e4.x + e4.y*e4.y + e4.z*e4.z + e4.w*e4.w;
        #pragma unroll
        for (int o = 16; o; o >>= 1) {
            num += __shfl_down_sync(0xffffffffu, num, o);
            nn  += __shfl_down_sync(0xffffffffu, nn,  o);
        }
        if (lane == 0) {
            float den = fmaxf(cn * sqrtf(nn), 1e-8f);
            s_sim[n] = num / den;
        }
    }
    __syncthreads();

    // top-K with jax.lax.top_k tie-break (lower index wins); rank is a permutation
    if (t < MCAND) {
        const float v = s_sim[t];
        int r = 0;
        for (int i = 0; i < MCAND; i++) {
            const float u = s_sim[i];
            r += (u > v) || (u == v && i < t);
        }
        if (r < KSEL) { s_selr[r] = s_ridx[t]; s_sele[r] = s_eidx[t]; }
    }
    __syncthreads();

    // mean of selected [rel ; ent]
    {
        float acc = 0.f;
        if (t < DD) {
            #pragma unroll 8
            for (int k = 0; k < KSEL; k++) acc += emb[(size_t)s_selr[k] * DD + t];
        } else {
            const int d = t - DD;
            #pragma unroll 8
            for (int k = 0; k < KSEL; k++) acc += emb[(size_t)s_sele[k] * DD + d];
        }
        s_mcat[t] = acc * (1.f / KSEL);
    }
    __syncthreads();

    // GEMV 256 -> 128 (+biases, tanh)
    for (int dd = 0; dd < 16; dd++) {
        const int d = w * 16 + dd;
        const float* wr = gcnW + (size_t)d * DMM;
        float pp = 0.f;
        #pragma unroll
        for (int c = lane; c < DMM; c += 32) pp += wr[c] * s_mcat[c];
        #pragma unroll
        for (int o = 16; o; o >>= 1) pp += __shfl_down_sync(0xffffffffu, pp, o);
        if (lane == 0)
            g_cat[(size_t)out_row * DMM + coff + d] = tanhf(pp + gbias[d] + gb[d]);
    }
}

// ---------------- SGEMM: C[M,N] = A[M,K] @ B[N,K]^T (+epilogue) ----------------
// tile 64x64, 256 threads, 4x4 per thread, BK=32, register-prefetch pipeline.
// EPI: 0 = +bias[n], 1 = relu(+bias[n]), 2 = +Cadd[m,n] + bias[n]
template <int EPI>
__global__ __launch_bounds__(256)
void sgemm_nt(const float* __restrict__ A, const float* __restrict__ Bm,
              float* __restrict__ C, int M, int N, int K,
              const float* __restrict__ bias, const float* __restrict__ Cadd)
{
    __shared__ __align__(16) float As[32][68];
    __shared__ __align__(16) float Bs[32][68];
    const int t  = threadIdx.x;
    const int m0 = blockIdx.y * 64;
    const int n0 = blockIdx.x * 64;

    const int lr = t >> 2;          // 0..63 (tile row for loading)
    const int lk = (t & 3) * 8;     // 0/8/16/24 (k offset for loading)
    const int tm = (t >> 4) * 4;    // compute row base
    const int tn = (t & 15) * 4;    // compute col base

    const bool am = (m0 + lr) < M;
    const float* Ab = A  + (size_t)(am ? (m0 + lr) : 0) * K + lk;
    const float* Bb = Bm + (size_t)(n0 + lr) * K + lk;

    float4 pa0, pa1, pb0, pb1;
    const float4 z4 = make_float4(0.f, 0.f, 0.f, 0.f);

    #define LOADT(kt)                                                        \
        { if (am) { pa0 = *(const float4*)(Ab + (kt) * 32);                  \
                    pa1 = *(const float4*)(Ab + (kt) * 32 + 4); }            \
          else    { pa0 = z4; pa1 = z4; }                                    \
          pb0 = *(const float4*)(Bb + (kt) * 32);                            \
          pb1 = *(const float4*)(Bb + (kt) * 32 + 4); }

    #define STORET()                                                         \
        { As[lk+0][lr]=pa0.x; As[lk+1][lr]=pa0.y; As[lk+2][lr]=pa0.z;        \
          As[lk+3][lr]=pa0.w; As[lk+4][lr]=pa1.x; As[lk+5][lr]=pa1.y;        \
          As[lk+6][lr]=pa1.z; As[lk+7][lr]=pa1.w;                            \
          Bs[lk+0][lr]=pb0.x; Bs[lk+1][lr]=pb0.y; Bs[lk+2][lr]=pb0.z;        \
          Bs[lk+3][lr]=pb0.w; Bs[lk+4][lr]=pb1.x; Bs[lk+5][lr]=pb1.y;        \
          Bs[lk+6][lr]=pb1.z; Bs[lk+7][lr]=pb1.w; }

    float acc[4][4] = {{0.f}};

    LOADT(0);
    STORET();
    __syncthreads();

    const int nkt = K >> 5;
    for (int kt = 0; kt < nkt; kt++) {
        if (kt + 1 < nkt) LOADT(kt + 1);
        #pragma unroll
        for (int k = 0; k < 32; k++) {
            const float4 a = *(const float4*)&As[k][tm];
            const float4 b = *(const float4*)&Bs[k][tn];
            acc[0][0] += a.x*b.x; acc[0][1] += a.x*b.y; acc[0][2] += a.x*b.z; acc[0][3] += a.x*b.w;
            acc[1][0] += a.y*b.x; acc[1][1] += a.y*b.y; acc[1][2] += a.y*b.z; acc[1][3] += a.y*b.w;
            acc[2][0] += a.z*b.x; acc[2][1] += a.z*b.y; acc[2][2] += a.z*b.z; acc[2][3] += a.z*b.w;
            acc[3][0] += a.w*b.x; acc[3][1] += a.w*b.y; acc[3][2] += a.w*b.z; acc[3][3] += a.w*b.w;
        }
        if (kt + 1 < nkt) {
            __syncthreads();
            STORET();
            __syncthreads();
        }
    }
    #undef LOADT
    #undef STORET

    const int nIdx = n0 + tn;
    const float4 bv4 = *(const float4*)(bias + nIdx);
    #pragma unroll
    for (int i = 0; i < 4; i++) {
        const int m = m0 + tm + i;
        if (m < M) {
            float4 v = make_float4(acc[i][0], acc[i][1], acc[i][2], acc[i][3]);
            v.x += bv4.x; v.y += bv4.y; v.z += bv4.z; v.w += bv4.w;
            if (EPI == 1) {
                v.x = fmaxf(v.x, 0.f); v.y = fmaxf(v.y, 0.f);
                v.z = fmaxf(v.z, 0.f); v.w = fmaxf(v.w, 0.f);
            } else if (EPI == 2) {
                const float4 cadd = *(const float4*)(Cadd + (size_t)m * N + nIdx);
                v.x += cadd.x; v.y += cadd.y; v.z += cadd.z; v.w += cadd.w;
            }
            *(float4*)(C + (size_t)m * N + nIdx) = v;
        }
    }
}

// ---------------- residual + layernorm ----------------
__global__ __launch_bounds__(256)
void ln_kernel(const float* __restrict__ g, const float* __restrict__ b)
{
    const int row = blockIdx.x;
    const int t = threadIdx.x;
    const int lane = t & 31, w = t >> 5;
    const float x = g_cat[(size_t)row * DMM + t];
    const float y = g_h2[(size_t)row * DMM + t] + x;

    __shared__ float s1[8], s2[8];
    __shared__ float s_mu, s_rs;
    float s = y, ss = y * y;
    #pragma unroll
    for (int o = 16; o; o >>= 1) {
        s  += __shfl_down_sync(0xffffffffu, s,  o);
        ss += __shfl_down_sync(0xffffffffu, ss, o);
    }
    if (lane == 0) { s1[w] = s; s2[w] = ss; }
    __syncthreads();
    if (t == 0) {
        float S = 0.f, SS = 0.f;
        #pragma unroll
        for (int i = 0; i < 8; i++) { S += s1[i]; SS += s2[i]; }
        const float mu = S / DMM;
        const float var = SS / DMM - mu * mu;
        s_mu = mu; s_rs = rsqrtf(var + 1e-5f);
    }
    __syncthreads();
    const float o = g[t] * (y - s_mu) * s_rs + b[t];
    if (row < NQ) g_qg[(size_t)row * DMM + t] = o;
    else          g_sse[(size_t)(row - NQ) * DMM + t] = o;
}

// ---------------- support mean + l2norm ----------------
__global__ __launch_bounds__(256)
void support_reduce()
{
    const int t = threadIdx.x;
    const int lane = t & 31, w = t >> 5;
    float s = 0.f;
    #pragma unroll
    for (int r = 0; r < FEWS; r++) s += g_sse[r * DMM + t];
    s *= (1.f / FEWS);
    g_sg[t] = s;

    __shared__ float s1[8];
    __shared__ float s_n;
    float p = s * s;
    #pragma unroll
    for (int o = 16; o; o >>= 1) p += __shfl_down_sync(0xffffffffu, p, o);
    if (lane == 0) s1[w] = p;
    __syncthreads();
    if (t == 0) {
        float S = 0.f;
        #pragma unroll
        for (int i = 0; i < 8; i++) S += s1[i];
        s_n = fmaxf(sqrtf(S), 1e-12f);
    }
    __syncthreads();
    g_sgn[t] = s / s_n;
}

// ---------------- LSTM step 0 on compacted gates ----------------
__global__ __launch_bounds__(256)
void e0_kernel()
{
    const int idx = blockIdx.x * 256 + threadIdx.x;   // NQ*256
    const int row = idx >> 8, j = idx & 255;
    const float* gr = g_GxC + (size_t)row * GC;
    const float ig = 1.f / (1.f + expf(-gr[j]));
    const float gg = tanhf(gr[512 + j]);
    const float c  = ig * gg;
    g_c0[idx] = c;
    const float og = 1.f / (1.f + expf(-gr[768 + j]));
    g_hr[idx] = g_qg[idx] + og * tanhf(c);
}

// ---------------- LSTM step 1 + l2norm + final dot ----------------
__global__ __launch_bounds__(256)
void final_kernel(float* __restrict__ out)
{
    const int row = blockIdx.x;
    const int t = threadIdx.x;
    const int lane = t & 31, w = t >> 5;
    const float* gr = g_gates + (size_t)row * GC;
    const float ig = 1.f / (1.f + expf(-gr[t]));
    const float fg = 1.f / (1.f + expf(-gr[256 + t]));
    const float gg = tanhf(gr[512 + t]);
    const float og = 1.f / (1.f + expf(-gr[768 + t]));
    const float c  = fg * g_c0[(size_t)row * DMM + t] + ig * gg;
    const float h  = g_qg[(size_t)row * DMM + t] + og * tanhf(c);

    float d = h * g_sgn[t];
    float n2 = h * h;
    __shared__ float sd[8], sn[8];
    #pragma unroll
    for (int o = 16; o; o >>= 1) {
        d  += __shfl_down_sync(0xffffffffu, d,  o);
        n2 += __shfl_down_sync(0xffffffffu, n2, o);
    }
    if (lane == 0) { sd[w] = d; sn[w] = n2; }
    __syncthreads();
    if (t == 0) {
        float DT = 0.f, NT = 0.f;
        #pragma unroll
        for (int i = 0; i < 8; i++) { DT += sd[i]; NT += sn[i]; }
        out[row] = DT / fmaxf(sqrtf(NT), 1e-12f);
    }
}

// ---------------- launch ----------------
extern "C" void kernel_launch(void* const* d_in, const int* in_sizes, int n_in,
                              void* d_out, int out_size)
{
    const int*   query   = (const int*)  d_in[0];
    const int*   support = (const int*)  d_in[1];
    const int*   qlc     = (const int*)  d_in[2];
    const int*   qrc     = (const int*)  d_in[4];
    const int*   slc     = (const int*)  d_in[6];
    const int*   src     = (const int*)  d_in[8];
    const float* emb     = (const float*)d_in[10];
    const float* gcnW    = (const float*)d_in[11];
    const float* gbias   = (const float*)d_in[12];
    const float* gb      = (const float*)d_in[13];
    const float* w1      = (const float*)d_in[14];
    const float* b1      = (const float*)d_in[15];
    const float* w2      = (const float*)d_in[16];
    const float* b2      = (const float*)d_in[17];
    const float* lng     = (const float*)d_in[18];
    const float* lnb     = (const float*)d_in[19];
    const float* Wih     = (const float*)d_in[20];
    const float* Whh     = (const float*)d_in[21];
    const float* bih     = (const float*)d_in[22];
    const float* bhh     = (const float*)d_in[23];
    float* out = (float*)d_out;

    float *p_cat, *p_h1, *p_h2, *p_qg, *p_WihC, *p_WhhC, *p_bsumC, *p_svec;
    float *p_GxC, *p_gates, *p_hr;
    cudaGetSymbolAddress((void**)&p_cat,   g_cat);
    cudaGetSymbolAddress((void**)&p_h1,    g_h1);
    cudaGetSymbolAddress((void**)&p_h2,    g_h2);
    cudaGetSymbolAddress((void**)&p_qg,    g_qg);
    cudaGetSymbolAddress((void**)&p_WihC,  g_WihC);
    cudaGetSymbolAddress((void**)&p_WhhC,  g_WhhC);
    cudaGetSymbolAddress((void**)&p_bsumC, g_bsumC);
    cudaGetSymbolAddress((void**)&p_svec,  g_svec);
    cudaGetSymbolAddress((void**)&p_GxC,   g_GxC);
    cudaGetSymbolAddress((void**)&p_gates, g_gates);
    cudaGetSymbolAddress((void**)&p_hr,    g_hr);

    compact_kernel<<<GC * DMM / 256, 256>>>(Wih, Whh, bih, bhh);
    neighbor_all<<<NBLK, 256>>>(emb, qlc, qrc, slc, src, query, support, gcnW, gbias, gb);

    // support encoder (batched query + support rows)
    sgemm_nt<1><<<dim3(DFF / 64, (RTOT + 63) / 64), 256>>>(p_cat, w1, p_h1, RTOT, DFF, DMM, b1, nullptr);
    sgemm_nt<0><<<dim3(DMM / 64, (RTOT + 63) / 64), 256>>>(p_h1, w2, p_h2, RTOT, DMM, DFF, b2, nullptr);
    ln_kernel<<<RTOT, 256>>>(lng, lnb);
    support_reduce<<<1, 256>>>();
    svec_kernel<<<GC / 8, 256>>>(Whh);

    // query encoder on compacted gate columns
    sgemm_nt<0><<<dim3(GC / 64, NQ / 64), 256>>>(p_qg, p_WihC, p_GxC, NQ, GC, DMM, p_bsumC, nullptr);
    e0_kernel<<<NQ * DMM / 256, 256>>>();
    sgemm_nt<2><<<dim3(GC / 64, NQ / 64), 256>>>(p_hr, p_WhhC, p_gates, NQ, GC, DMM, p_svec, p_GxC);
    final_kernel<<<NQ, 256>>>(out);
}

// round 4
// speedup vs baseline: 2.7929x; 1.1286x over previous
#include <cuda_runtime.h>
#include <math.h>

#define NQ    1024
#define FEWS  5
#define MCAND 200
#define KSEL  32
#define DD    128
#define DMM   256
#define DFF   512
#define HHH   512
#define GC    1024            // compacted gate columns (4 x 256)
#define RTOT  (NQ + FEWS)     // 1029
#define NBLK  (2*NQ + 2*FEWS) // 2058 neighbor tasks

// ---------------- workspace (device globals; no allocations) ----------------
__device__ float g_cat  [RTOT * DMM];
__device__ float g_h1   [RTOT * DFF];
__device__ float g_h2   [2 * RTOT * DMM];   // 2 split-K planes
__device__ float g_qg   [NQ   * DMM];
__device__ float g_sse  [FEWS * DMM];
__device__ float g_sg   [DMM];
__device__ float g_sgn  [DMM];
__device__ float g_WihC [GC * DMM];
__device__ float g_WhhC [GC * DMM];
__device__ float g_bsumC[GC];
__device__ float g_svec [GC];
__device__ float g_GxC  [NQ * GC];
__device__ float g_gates[NQ * GC];
__device__ float g_c0   [NQ * DMM];
__device__ float g_hr   [NQ * DMM];

__device__ __forceinline__ int orig_col(int r) { return ((r >> 8) << 9) + (r & 255); }

// ---------------- weight compaction: live gate columns only ----------------
__global__ __launch_bounds__(256)
void compact_kernel(const float* __restrict__ Wih, const float* __restrict__ Whh,
                    const float* __restrict__ bih, const float* __restrict__ bhh)
{
    const int idx = blockIdx.x * 256 + threadIdx.x;   // GC*DMM threads
    const int r = idx >> 8, c = idx & 255;
    const int o = orig_col(r);
    g_WihC[idx] = Wih[(size_t)o * DMM + c];
    g_WhhC[idx] = Whh[(size_t)o * HHH + c];
    if (c == 0) g_bsumC[r] = bih[o] + bhh[o];
}

// ---------------- svec[r] = dot(Whh[orig(r), 256:512], support_g) ----------------
__global__ __launch_bounds__(256)
void svec_kernel(const float* __restrict__ Whh)
{
    const int lane = threadIdx.x & 31;
    const int r = blockIdx.x * 8 + (threadIdx.x >> 5);
    const int o = orig_col(r);
    const float* wr = Whh + (size_t)o * HHH + DMM;
    float p = 0.f;
    #pragma unroll
    for (int c = lane; c < DMM; c += 32) p += wr[c] * g_sg[c];
    #pragma unroll
    for (int off = 16; off; off >>= 1) p += __shfl_down_sync(0xffffffffu, p, off);
    if (lane == 0) g_svec[r] = p;
}

// ---------------- neighbor encoder: all 2058 tasks in one launch ----------------
__global__ __launch_bounds__(256)
void neighbor_all(const float* __restrict__ emb,
                  const int* __restrict__ qlc, const int* __restrict__ qrc,
                  const int* __restrict__ slc, const int* __restrict__ src,
                  const int* __restrict__ query, const int* __restrict__ support,
                  const float* __restrict__ gcnW,
                  const float* __restrict__ gbias, const float* __restrict__ gb)
{
    const int b = blockIdx.x;
    const int t = threadIdx.x;
    const int lane = t & 31;
    const int w = t >> 5;

    const int* conn_row;
    int cid, out_row, coff;
    if (b < NQ)            { conn_row = qlc + (size_t)b * MCAND * 2;            cid = query[b * 2 + 0];           out_row = b;                 coff = 0;  }
    else if (b < 2 * NQ)   { int rb = b - NQ;   conn_row = qrc + (size_t)rb * MCAND * 2; cid = query[rb * 2 + 1]; out_row = rb;                coff = DD; }
    else if (b < 2*NQ+FEWS){ int rb = b - 2*NQ; conn_row = slc + (size_t)rb * MCAND * 2; cid = support[rb*2 + 0]; out_row = NQ + rb;           coff = 0;  }
    else                   { int rb = b - 2*NQ - FEWS; conn_row = src + (size_t)rb * MCAND * 2; cid = support[rb*2 + 1]; out_row = NQ + rb;    coff = DD; }

    __shared__ __align__(16) float s_center[DD];
    __shared__ float s_sim [MCAND];
    __shared__ int   s_ridx[MCAND];
    __shared__ int   s_eidx[MCAND];
    __shared__ int   s_selr[KSEL];
    __shared__ int   s_sele[KSEL];
    __shared__ float s_mcat[DMM];
    __shared__ float s_red[8];
    __shared__ float s_cn;

    for (int n = t; n < MCAND; n += 256) {
        s_ridx[n] = conn_row[n * 2 + 0];
        s_eidx[n] = conn_row[n * 2 + 1];
    }
    float cv = 0.f;
    if (t < DD) { cv = emb[(size_t)cid * DD + t]; s_center[t] = cv; }

    float p = cv * cv;
    #pragma unroll
    for (int o = 16; o; o >>= 1) p += __shfl_down_sync(0xffffffffu, p, o);
    if (lane == 0) s_red[w] = p;
    __syncthreads();
    if (t == 0) {
        float s = 0.f;
        #pragma unroll
        for (int i = 0; i < 8; i++) s += s_red[i];
        s_cn = sqrtf(s);
    }
    __syncthreads();
    const float cn = s_cn;

    const float4 c4 = *(const float4*)(s_center + lane * 4);
    for (int n = w; n < MCAND; n += 8) {
        const float4 e4 = *(const float4*)(emb + (size_t)s_eidx[n] * DD + lane * 4);
        float num = e4.x*c4.x + e4.y*c4.y + e4.z*c4.z + e4.w*c4.w;
        float nn  = e4.x*e4.x + e4.y*e4.y + e4.z*e4.z + e4.w*e4.w;
        #pragma unroll
        for (int o = 16; o; o >>= 1) {
            num += __shfl_down_sync(0xffffffffu, num, o);
            nn  += __shfl_down_sync(0xffffffffu, nn,  o);
        }
        if (lane == 0) {
            float den = fmaxf(cn * sqrtf(nn), 1e-8f);
            s_sim[n] = num / den;
        }
    }
    __syncthreads();

    // top-K with jax.lax.top_k tie-break (lower index wins); rank is a permutation
    if (t < MCAND) {
        const float v = s_sim[t];
        int r = 0;
        for (int i = 0; i < MCAND; i++) {
            const float u = s_sim[i];
            r += (u > v) || (u == v && i < t);
        }
        if (r < KSEL) { s_selr[r] = s_ridx[t]; s_sele[r] = s_eidx[t]; }
    }
    __syncthreads();

    // mean of selected [rel ; ent]
    {
        float acc = 0.f;
        if (t < DD) {
            #pragma unroll 8
            for (int k = 0; k < KSEL; k++) acc += emb[(size_t)s_selr[k] * DD + t];
        } else {
            const int d = t - DD;
            #pragma unroll 8
            for (int k = 0; k < KSEL; k++) acc += emb[(size_t)s_sele[k] * DD + d];
        }
        s_mcat[t] = acc * (1.f / KSEL);
    }
    __syncthreads();

    // GEMV 256 -> 128 (+biases, tanh)
    for (int dd = 0; dd < 16; dd++) {
        const int d = w * 16 + dd;
        const float* wr = gcnW + (size_t)d * DMM;
        float pp = 0.f;
        #pragma unroll
        for (int c = lane; c < DMM; c += 32) pp += wr[c] * s_mcat[c];
        #pragma unroll
        for (int o = 16; o; o >>= 1) pp += __shfl_down_sync(0xffffffffu, pp, o);
        if (lane == 0)
            g_cat[(size_t)out_row * DMM + coff + d] = tanhf(pp + gbias[d] + gb[d]);
    }
}

// ---------------- SGEMM: C[M,N] = A[M,K] @ B[N,K]^T (+epilogue) ----------------
// tile 64x64, 256 threads, 4x4 per thread, BK=32, DOUBLE-BUFFERED smem
// (1 barrier per k-tile). gridDim.z = split-K factor; plane z writes C + z*M*N.
// EPI: 0 = +bias[n], 1 = relu(+bias[n]), 2 = +Cadd[m,n] + bias[n], 3 = raw
template <int EPI>
__global__ __launch_bounds__(256)
void sgemm_nt(const float* __restrict__ A, const float* __restrict__ Bm,
              float* __restrict__ C, int M, int N, int K,
              const float* __restrict__ bias, const float* __restrict__ Cadd)
{
    __shared__ __align__(16) float As[2][32][68];
    __shared__ __align__(16) float Bs[2][32][68];
    const int t  = threadIdx.x;
    const int m0 = blockIdx.y * 64;
    const int n0 = blockIdx.x * 64;
    const int ks = K / gridDim.z;          // K slice for this z-plane
    const int kb = blockIdx.z * ks;

    const int lr = t >> 2;          // 0..63 (tile row for loading)
    const int lk = (t & 3) * 8;     // 0/8/16/24 (k offset for loading)
    const int tm = (t >> 4) * 4;    // compute row base
    const int tn = (t & 15) * 4;    // compute col base

    const bool am = (m0 + lr) < M;
    const float* Ab = A  + (size_t)(am ? (m0 + lr) : 0) * K + kb + lk;
    const float* Bb = Bm + (size_t)(n0 + lr) * K + kb + lk;

    float4 pa0, pa1, pb0, pb1;
    const float4 z4 = make_float4(0.f, 0.f, 0.f, 0.f);

    #define LOADT(kt)                                                        \
        { if (am) { pa0 = *(const float4*)(Ab + (kt) * 32);                  \
                    pa1 = *(const float4*)(Ab + (kt) * 32 + 4); }            \
          else    { pa0 = z4; pa1 = z4; }                                    \
          pb0 = *(const float4*)(Bb + (kt) * 32);                            \
          pb1 = *(const float4*)(Bb + (kt) * 32 + 4); }

    #define STORET(buf)                                                      \
        { As[buf][lk+0][lr]=pa0.x; As[buf][lk+1][lr]=pa0.y;                  \
          As[buf][lk+2][lr]=pa0.z; As[buf][lk+3][lr]=pa0.w;                  \
          As[buf][lk+4][lr]=pa1.x; As[buf][lk+5][lr]=pa1.y;                  \
          As[buf][lk+6][lr]=pa1.z; As[buf][lk+7][lr]=pa1.w;                  \
          Bs[buf][lk+0][lr]=pb0.x; Bs[buf][lk+1][lr]=pb0.y;                  \
          Bs[buf][lk+2][lr]=pb0.z; Bs[buf][lk+3][lr]=pb0.w;                  \
          Bs[buf][lk+4][lr]=pb1.x; Bs[buf][lk+5][lr]=pb1.y;                  \
          Bs[buf][lk+6][lr]=pb1.z; Bs[buf][lk+7][lr]=pb1.w; }

    float acc[4][4] = {{0.f}};

    LOADT(0);
    STORET(0);
    __syncthreads();

    const int nkt = ks >> 5;
    for (int kt = 0; kt < nkt; kt++) {
        const int cur = kt & 1;
        if (kt + 1 < nkt) LOADT(kt + 1);
        #pragma unroll
        for (int k = 0; k < 32; k++) {
            const float4 a = *(const float4*)&As[cur][k][tm];
            const float4 b = *(const float4*)&Bs[cur][k][tn];
            acc[0][0] += a.x*b.x; acc[0][1] += a.x*b.y; acc[0][2] += a.x*b.z; acc[0][3] += a.x*b.w;
            acc[1][0] += a.y*b.x; acc[1][1] += a.y*b.y; acc[1][2] += a.y*b.z; acc[1][3] += a.y*b.w;
            acc[2][0] += a.z*b.x; acc[2][1] += a.z*b.y; acc[2][2] += a.z*b.z; acc[2][3] += a.z*b.w;
            acc[3][0] += a.w*b.x; acc[3][1] += a.w*b.y; acc[3][2] += a.w*b.z; acc[3][3] += a.w*b.w;
        }
        if (kt + 1 < nkt) {
            STORET(cur ^ 1);         // other buffer: safe while peers compute cur
            __syncthreads();
        }
    }
    #undef LOADT
    #undef STORET

    C += (size_t)blockIdx.z * M * N;
    const int nIdx = n0 + tn;
    float4 bv4 = z4;
    if (EPI != 3) bv4 = *(const float4*)(bias + nIdx);
    #pragma unroll
    for (int i = 0; i < 4; i++) {
        const int m = m0 + tm + i;
        if (m < M) {
            float4 v = make_float4(acc[i][0], acc[i][1], acc[i][2], acc[i][3]);
            v.x += bv4.x; v.y += bv4.y; v.z += bv4.z; v.w += bv4.w;
            if (EPI == 1) {
                v.x = fmaxf(v.x, 0.f); v.y = fmaxf(v.y, 0.f);
                v.z = fmaxf(v.z, 0.f); v.w = fmaxf(v.w, 0.f);
            } else if (EPI == 2) {
                const float4 cadd = *(const float4*)(Cadd + (size_t)m * N + nIdx);
                v.x += cadd.x; v.y += cadd.y; v.z += cadd.z; v.w += cadd.w;
            }
            *(float4*)(C + (size_t)m * N + nIdx) = v;
        }
    }
}

// ---------------- residual + layernorm (sums the 2 split-K planes + b2) ----------------
__global__ __launch_bounds__(256)
void ln_kernel(const float* __restrict__ g, const float* __restrict__ b,
               const float* __restrict__ b2)
{
    const int row = blockIdx.x;
    const int t = threadIdx.x;
    const int lane = t & 31, w = t >> 5;
    const float x = g_cat[(size_t)row * DMM + t];
    const float y = g_h2[(size_t)row * DMM + t]
                  + g_h2[(size_t)(RTOT + row) * DMM + t]
                  + b2[t] + x;

    __shared__ float s1[8], s2[8];
    __shared__ float s_mu, s_rs;
    float s = y, ss = y * y;
    #pragma unroll
    for (int o = 16; o; o >>= 1) {
        s  += __shfl_down_sync(0xffffffffu, s,  o);
        ss += __shfl_down_sync(0xffffffffu, ss, o);
    }
    if (lane == 0) { s1[w] = s; s2[w] = ss; }
    __syncthreads();
    if (t == 0) {
        float S = 0.f, SS = 0.f;
        #pragma unroll
        for (int i = 0; i < 8; i++) { S += s1[i]; SS += s2[i]; }
        const float mu = S / DMM;
        const float var = SS / DMM - mu * mu;
        s_mu = mu; s_rs = rsqrtf(var + 1e-5f);
    }
    __syncthreads();
    const float o = g[t] * (y - s_mu) * s_rs + b[t];
    if (row < NQ) g_qg[(size_t)row * DMM + t] = o;
    else          g_sse[(size_t)(row - NQ) * DMM + t] = o;
}

// ---------------- support mean + l2norm ----------------
__global__ __launch_bounds__(256)
void support_reduce()
{
    const int t = threadIdx.x;
    const int lane = t & 31, w = t >> 5;
    float s = 0.f;
    #pragma unroll
    for (int r = 0; r < FEWS; r++) s += g_sse[r * DMM + t];
    s *= (1.f / FEWS);
    g_sg[t] = s;

    __shared__ float s1[8];
    __shared__ float s_n;
    float p = s * s;
    #pragma unroll
    for (int o = 16; o; o >>= 1) p += __shfl_down_sync(0xffffffffu, p, o);
    if (lane == 0) s1[w] = p;
    __syncthreads();
    if (t == 0) {
        float S = 0.f;
        #pragma unroll
        for (int i = 0; i < 8; i++) S += s1[i];
        s_n = fmaxf(sqrtf(S), 1e-12f);
    }
    __syncthreads();
    g_sgn[t] = s / s_n;
}

// ---------------- LSTM step 0 on compacted gates ----------------
__global__ __launch_bounds__(256)
void e0_kernel()
{
    const int idx = blockIdx.x * 256 + threadIdx.x;   // NQ*256
    const int row = idx >> 8, j = idx & 255;
    const float* gr = g_GxC + (size_t)row * GC;
    const float ig = 1.f / (1.f + expf(-gr[j]));
    const float gg = tanhf(gr[512 + j]);
    const float c  = ig * gg;
    g_c0[idx] = c;
    const float og = 1.f / (1.f + expf(-gr[768 + j]));
    g_hr[idx] = g_qg[idx] + og * tanhf(c);
}

// ---------------- LSTM step 1 + l2norm + final dot ----------------
__global__ __launch_bounds__(256)
void final_kernel(float* __restrict__ out)
{
    const int row = blockIdx.x;
    const int t = threadIdx.x;
    const int lane = t & 31, w = t >> 5;
    const float* gr = g_gates + (size_t)row * GC;
    const float ig = 1.f / (1.f + expf(-gr[t]));
    const float fg = 1.f / (1.f + expf(-gr[256 + t]));
    const float gg = tanhf(gr[512 + t]);
    const float og = 1.f / (1.f + expf(-gr[768 + t]));
    const float c  = fg * g_c0[(size_t)row * DMM + t] + ig * gg;
    const float h  = g_qg[(size_t)row * DMM + t] + og * tanhf(c);

    float d = h * g_sgn[t];
    float n2 = h * h;
    __shared__ float sd[8], sn[8];
    #pragma unroll
    for (int o = 16; o; o >>= 1) {
        d  += __shfl_down_sync(0xffffffffu, d,  o);
        n2 += __shfl_down_sync(0xffffffffu, n2, o);
    }
    if (lane == 0) { sd[w] = d; sn[w] = n2; }
    __syncthreads();
    if (t == 0) {
        float DT = 0.f, NT = 0.f;
        #pragma unroll
        for (int i = 0; i < 8; i++) { DT += sd[i]; NT += sn[i]; }
        out[row] = DT / fmaxf(sqrtf(NT), 1e-12f);
    }
}

// ---------------- launch ----------------
extern "C" void kernel_launch(void* const* d_in, const int* in_sizes, int n_in,
                              void* d_out, int out_size)
{
    const int*   query   = (const int*)  d_in[0];
    const int*   support = (const int*)  d_in[1];
    const int*   qlc     = (const int*)  d_in[2];
    const int*   qrc     = (const int*)  d_in[4];
    const int*   slc     = (const int*)  d_in[6];
    const int*   src     = (const int*)  d_in[8];
    const float* emb     = (const float*)d_in[10];
    const float* gcnW    = (const float*)d_in[11];
    const float* gbias   = (const float*)d_in[12];
    const float* gb      = (const float*)d_in[13];
    const float* w1      = (const float*)d_in[14];
    const float* b1      = (const float*)d_in[15];
    const float* w2      = (const float*)d_in[16];
    const float* b2      = (const float*)d_in[17];
    const float* lng     = (const float*)d_in[18];
    const float* lnb     = (const float*)d_in[19];
    const float* Wih     = (const float*)d_in[20];
    const float* Whh     = (const float*)d_in[21];
    const float* bih     = (const float*)d_in[22];
    const float* bhh     = (const float*)d_in[23];
    float* out = (float*)d_out;

    float *p_cat, *p_h1, *p_h2, *p_qg, *p_WihC, *p_WhhC, *p_bsumC, *p_svec;
    float *p_GxC, *p_gates, *p_hr;
    cudaGetSymbolAddress((void**)&p_cat,   g_cat);
    cudaGetSymbolAddress((void**)&p_h1,    g_h1);
    cudaGetSymbolAddress((void**)&p_h2,    g_h2);
    cudaGetSymbolAddress((void**)&p_qg,    g_qg);
    cudaGetSymbolAddress((void**)&p_WihC,  g_WihC);
    cudaGetSymbolAddress((void**)&p_WhhC,  g_WhhC);
    cudaGetSymbolAddress((void**)&p_bsumC, g_bsumC);
    cudaGetSymbolAddress((void**)&p_svec,  g_svec);
    cudaGetSymbolAddress((void**)&p_GxC,   g_GxC);
    cudaGetSymbolAddress((void**)&p_gates, g_gates);
    cudaGetSymbolAddress((void**)&p_hr,    g_hr);

    compact_kernel<<<GC * DMM / 256, 256>>>(Wih, Whh, bih, bhh);
    neighbor_all<<<NBLK, 256>>>(emb, qlc, qrc, slc, src, query, support, gcnW, gbias, gb);

    // support encoder (batched query + support rows)
    sgemm_nt<1><<<dim3(DFF / 64, (RTOT + 63) / 64), 256>>>(p_cat, w1, p_h1, RTOT, DFF, DMM, b1, nullptr);
    // split-K=2: 2 partial planes (68 -> 136 blocks); summed with b2 in ln_kernel
    sgemm_nt<3><<<dim3(DMM / 64, (RTOT + 63) / 64, 2), 256>>>(p_h1, w2, p_h2, RTOT, DMM, DFF, nullptr, nullptr);
    ln_kernel<<<RTOT, 256>>>(lng, lnb, b2);
    support_reduce<<<1, 256>>>();
    svec_kernel<<<GC / 8, 256>>>(Whh);

    // query encoder on compacted gate columns
    sgemm_nt<0><<<dim3(GC / 64, NQ / 64), 256>>>(p_qg, p_WihC, p_GxC, NQ, GC, DMM, p_bsumC, nullptr);
    e0_kernel<<<NQ * DMM / 256, 256>>>();
    sgemm_nt<2><<<dim3(GC / 64, NQ / 64), 256>>>(p_hr, p_WhhC, p_gates, NQ, GC, DMM, p_svec, p_GxC);
    final_kernel<<<NQ, 256>>>(out);
}

// round 5
// speedup vs baseline: 3.0707x; 1.0995x over previous
#include <cuda_runtime.h>
#include <math.h>
#include <stdint.h>

#define NQ    1024
#define FEWS  5
#define MCAND 200
#define KSEL  32
#define DD    128
#define DMM   256
#define DFF   512
#define HHH   512
#define GC    1024            // compacted gate columns (4 x 256)
#define RTOT  (NQ + FEWS)     // 1029
#define NBLK  (2*NQ + 2*FEWS) // 2058 neighbor tasks

// ---------------- workspace (device globals; no allocations) ----------------
__device__ float g_cat  [RTOT * DMM];
__device__ float g_h1   [RTOT * DFF];
__device__ float g_h2   [2 * RTOT * DMM];   // 2 split-K planes
__device__ float g_qg   [NQ   * DMM];
__device__ float g_sse  [FEWS * DMM];
__device__ float g_sg   [DMM];
__device__ float g_sgn  [DMM];
__device__ float g_WihC [GC * DMM];
__device__ float g_WhhC [GC * DMM];
__device__ float g_bsumC[GC];
__device__ float g_svec [GC];
__device__ float g_GxC  [NQ * GC];
__device__ float g_gates[NQ * GC];
__device__ float g_c0   [NQ * DMM];
__device__ float g_hr   [NQ * DMM];

__device__ __forceinline__ int orig_col(int r) { return ((r >> 8) << 9) + (r & 255); }

__device__ __forceinline__ uint32_t f2tf(float x) {
    uint32_t r;
    asm("cvt.rna.tf32.f32 %0, %1;" : "=r"(r) : "f"(x));
    return r;
}

__device__ __forceinline__ void mma8(float* c, const uint4& a, const uint2& b) {
    asm volatile(
        "mma.sync.aligned.m16n8k8.row.col.f32.tf32.tf32.f32 "
        "{%0,%1,%2,%3}, {%4,%5,%6,%7}, {%8,%9}, {%0,%1,%2,%3};"
        : "+f"(c[0]), "+f"(c[1]), "+f"(c[2]), "+f"(c[3])
        : "r"(a.x), "r"(a.y), "r"(a.z), "r"(a.w), "r"(b.x), "r"(b.y));
}

// ---------------- weight compaction: live gate columns only ----------------
__global__ __launch_bounds__(256)
void compact_kernel(const float* __restrict__ Wih, const float* __restrict__ Whh,
                    const float* __restrict__ bih, const float* __restrict__ bhh)
{
    const int idx = blockIdx.x * 256 + threadIdx.x;   // GC*DMM threads
    const int r = idx >> 8, c = idx & 255;
    const int o = orig_col(r);
    g_WihC[idx] = Wih[(size_t)o * DMM + c];
    g_WhhC[idx] = Whh[(size_t)o * HHH + c];
    if (c == 0) g_bsumC[r] = bih[o] + bhh[o];
}

// ---------------- svec[r] = dot(Whh[orig(r), 256:512], support_g) ----------------
__global__ __launch_bounds__(256)
void svec_kernel(const float* __restrict__ Whh)
{
    const int lane = threadIdx.x & 31;
    const int r = blockIdx.x * 8 + (threadIdx.x >> 5);
    const int o = orig_col(r);
    const float* wr = Whh + (size_t)o * HHH + DMM;
    float p = 0.f;
    #pragma unroll
    for (int c = lane; c < DMM; c += 32) p += wr[c] * g_sg[c];
    #pragma unroll
    for (int off = 16; off; off >>= 1) p += __shfl_down_sync(0xffffffffu, p, off);
    if (lane == 0) g_svec[r] = p;
}

// ---------------- neighbor encoder: all 2058 tasks in one launch ----------------
__global__ __launch_bounds__(256)
void neighbor_all(const float* __restrict__ emb,
                  const int* __restrict__ qlc, const int* __restrict__ qrc,
                  const int* __restrict__ slc, const int* __restrict__ src,
                  const int* __restrict__ query, const int* __restrict__ support,
                  const float* __restrict__ gcnW,
                  const float* __restrict__ gbias, const float* __restrict__ gb)
{
    const int b = blockIdx.x;
    const int t = threadIdx.x;
    const int lane = t & 31;
    const int w = t >> 5;

    const int* conn_row;
    int cid, out_row, coff;
    if (b < NQ)            { conn_row = qlc + (size_t)b * MCAND * 2;            cid = query[b * 2 + 0];           out_row = b;                 coff = 0;  }
    else if (b < 2 * NQ)   { int rb = b - NQ;   conn_row = qrc + (size_t)rb * MCAND * 2; cid = query[rb * 2 + 1]; out_row = rb;                coff = DD; }
    else if (b < 2*NQ+FEWS){ int rb = b - 2*NQ; conn_row = slc + (size_t)rb * MCAND * 2; cid = support[rb*2 + 0]; out_row = NQ + rb;           coff = 0;  }
    else                   { int rb = b - 2*NQ - FEWS; conn_row = src + (size_t)rb * MCAND * 2; cid = support[rb*2 + 1]; out_row = NQ + rb;    coff = DD; }

    __shared__ __align__(16) float s_center[DD];
    __shared__ float s_sim [MCAND];
    __shared__ int   s_ridx[MCAND];
    __shared__ int   s_eidx[MCAND];
    __shared__ int   s_selr[KSEL];
    __shared__ int   s_sele[KSEL];
    __shared__ float s_mcat[DMM];
    __shared__ float s_red[8];
    __shared__ float s_cn;

    for (int n = t; n < MCAND; n += 256) {
        s_ridx[n] = conn_row[n * 2 + 0];
        s_eidx[n] = conn_row[n * 2 + 1];
    }
    float cv = 0.f;
    if (t < DD) { cv = emb[(size_t)cid * DD + t]; s_center[t] = cv; }

    float p = cv * cv;
    #pragma unroll
    for (int o = 16; o; o >>= 1) p += __shfl_down_sync(0xffffffffu, p, o);
    if (lane == 0) s_red[w] = p;
    __syncthreads();
    if (t == 0) {
        float s = 0.f;
        #pragma unroll
        for (int i = 0; i < 8; i++) s += s_red[i];
        s_cn = sqrtf(s);
    }
    __syncthreads();
    const float cn = s_cn;

    const float4 c4 = *(const float4*)(s_center + lane * 4);
    for (int n = w; n < MCAND; n += 8) {
        const float4 e4 = *(const float4*)(emb + (size_t)s_eidx[n] * DD + lane * 4);
        float num = e4.x*c4.x + e4.y*c4.y + e4.z*c4.z + e4.w*c4.w;
        float nn  = e4.x*e4.x + e4.y*e4.y + e4.z*e4.z + e4.w*e4.w;
        #pragma unroll
        for (int o = 16; o; o >>= 1) {
            num += __shfl_down_sync(0xffffffffu, num, o);
            nn  += __shfl_down_sync(0xffffffffu, nn,  o);
        }
        if (lane == 0) {
            float den = fmaxf(cn * sqrtf(nn), 1e-8f);
            s_sim[n] = num / den;
        }
    }
    __syncthreads();

    // top-K with jax.lax.top_k tie-break (lower index wins); rank is a permutation
    if (t < MCAND) {
        const float v = s_sim[t];
        int r = 0;
        for (int i = 0; i < MCAND; i++) {
            const float u = s_sim[i];
            r += (u > v) || (u == v && i < t);
        }
        if (r < KSEL) { s_selr[r] = s_ridx[t]; s_sele[r] = s_eidx[t]; }
    }
    __syncthreads();

    // mean of selected [rel ; ent]
    {
        float acc = 0.f;
        if (t < DD) {
            #pragma unroll 8
            for (int k = 0; k < KSEL; k++) acc += emb[(size_t)s_selr[k] * DD + t];
        } else {
            const int d = t - DD;
            #pragma unroll 8
            for (int k = 0; k < KSEL; k++) acc += emb[(size_t)s_sele[k] * DD + d];
        }
        s_mcat[t] = acc * (1.f / KSEL);
    }
    __syncthreads();

    // GEMV 256 -> 128 (+biases, tanh)
    for (int dd = 0; dd < 16; dd++) {
        const int d = w * 16 + dd;
        const float* wr = gcnW + (size_t)d * DMM;
        float pp = 0.f;
        #pragma unroll
        for (int c = lane; c < DMM; c += 32) pp += wr[c] * s_mcat[c];
        #pragma unroll
        for (int o = 16; o; o >>= 1) pp += __shfl_down_sync(0xffffffffu, pp, o);
        if (lane == 0)
            g_cat[(size_t)out_row * DMM + coff + d] = tanhf(pp + gbias[d] + gb[d]);
    }
}

// ---------------- fp32 SGEMM (kept for G1/G2): C = A @ B^T ----------------
// tile 64x64, 256 threads, 4x4/thread, BK=32, double-buffered.
// EPI: 0 = +bias[n], 1 = relu(+bias[n]), 2 = +Cadd+bias, 3 = raw (split-K plane)
template <int EPI>
__global__ __launch_bounds__(256)
void sgemm_nt(const float* __restrict__ A, const float* __restrict__ Bm,
              float* __restrict__ C, int M, int N, int K,
              const float* __restrict__ bias, const float* __restrict__ Cadd)
{
    __shared__ __align__(16) float As[2][32][68];
    __shared__ __align__(16) float Bs[2][32][68];
    const int t  = threadIdx.x;
    const int m0 = blockIdx.y * 64;
    const int n0 = blockIdx.x * 64;
    const int ks = K / gridDim.z;
    const int kb = blockIdx.z * ks;

    const int lr = t >> 2;
    const int lk = (t & 3) * 8;
    const int tm = (t >> 4) * 4;
    const int tn = (t & 15) * 4;

    const bool am = (m0 + lr) < M;
    const float* Ab = A  + (size_t)(am ? (m0 + lr) : 0) * K + kb + lk;
    const float* Bb = Bm + (size_t)(n0 + lr) * K + kb + lk;

    float4 pa0, pa1, pb0, pb1;
    const float4 z4 = make_float4(0.f, 0.f, 0.f, 0.f);

    #define LOADT(kt)                                                        \
        { if (am) { pa0 = *(const float4*)(Ab + (kt) * 32);                  \
                    pa1 = *(const float4*)(Ab + (kt) * 32 + 4); }            \
          else    { pa0 = z4; pa1 = z4; }                                    \
          pb0 = *(const float4*)(Bb + (kt) * 32);                            \
          pb1 = *(const float4*)(Bb + (kt) * 32 + 4); }

    #define STORET(buf)                                                      \
        { As[buf][lk+0][lr]=pa0.x; As[buf][lk+1][lr]=pa0.y;                  \
          As[buf][lk+2][lr]=pa0.z; As[buf][lk+3][lr]=pa0.w;                  \
          As[buf][lk+4][lr]=pa1.x; As[buf][lk+5][lr]=pa1.y;                  \
          As[buf][lk+6][lr]=pa1.z; As[buf][lk+7][lr]=pa1.w;                  \
          Bs[buf][lk+0][lr]=pb0.x; Bs[buf][lk+1][lr]=pb0.y;                  \
          Bs[buf][lk+2][lr]=pb0.z; Bs[buf][lk+3][lr]=pb0.w;                  \
          Bs[buf][lk+4][lr]=pb1.x; Bs[buf][lk+5][lr]=pb1.y;                  \
          Bs[buf][lk+6][lr]=pb1.z; Bs[buf][lk+7][lr]=pb1.w; }

    float acc[4][4] = {{0.f}};

    LOADT(0);
    STORET(0);
    __syncthreads();

    const int nkt = ks >> 5;
    for (int kt = 0; kt < nkt; kt++) {
        const int cur = kt & 1;
        if (kt + 1 < nkt) LOADT(kt + 1);
        #pragma unroll
        for (int k = 0; k < 32; k++) {
            const float4 a = *(const float4*)&As[cur][k][tm];
            const float4 b = *(const float4*)&Bs[cur][k][tn];
            acc[0][0] += a.x*b.x; acc[0][1] += a.x*b.y; acc[0][2] += a.x*b.z; acc[0][3] += a.x*b.w;
            acc[1][0] += a.y*b.x; acc[1][1] += a.y*b.y; acc[1][2] += a.y*b.z; acc[1][3] += a.y*b.w;
            acc[2][0] += a.z*b.x; acc[2][1] += a.z*b.y; acc[2][2] += a.z*b.z; acc[2][3] += a.z*b.w;
            acc[3][0] += a.w*b.x; acc[3][1] += a.w*b.y; acc[3][2] += a.w*b.z; acc[3][3] += a.w*b.w;
        }
        if (kt + 1 < nkt) {
            STORET(cur ^ 1);
            __syncthreads();
        }
    }
    #undef LOADT
    #undef STORET

    C += (size_t)blockIdx.z * M * N;
    const int nIdx = n0 + tn;
    float4 bv4 = z4;
    if (EPI != 3) bv4 = *(const float4*)(bias + nIdx);
    #pragma unroll
    for (int i = 0; i < 4; i++) {
        const int m = m0 + tm + i;
        if (m < M) {
            float4 v = make_float4(acc[i][0], acc[i][1], acc[i][2], acc[i][3]);
            v.x += bv4.x; v.y += bv4.y; v.z += bv4.z; v.w += bv4.w;
            if (EPI == 1) {
                v.x = fmaxf(v.x, 0.f); v.y = fmaxf(v.y, 0.f);
                v.z = fmaxf(v.z, 0.f); v.w = fmaxf(v.w, 0.f);
            } else if (EPI == 2) {
                const float4 cadd = *(const float4*)(Cadd + (size_t)m * N + nIdx);
                v.x += cadd.x; v.y += cadd.y; v.z += cadd.z; v.w += cadd.w;
            }
            *(float4*)(C + (size_t)m * N + nIdx) = v;
        }
    }
}

// ---------------- tf32 tensor-core GEMM: C[M,N] = A[M,K] @ B[N,K]^T ----------------
// Block tile 64x64, BK=32, 8 warps (2m x 4n), warp tile 32x16 via m16n8k8 mma.
// smem holds tiles in FRAGMENT order: A frag = LDS.128/thread, B frag = LDS.64.
// EPI: 0 = +bias[n], 2 = +Cadd[m,n] + bias[n]
template <int EPI>
__global__ __launch_bounds__(256)
void tgemm(const float* __restrict__ A, const float* __restrict__ Bm,
           float* __restrict__ C, int M, int N, int K,
           const float* __restrict__ bias, const float* __restrict__ Cadd)
{
    // A: [buf][(mt*4 + ks)*128 + lane*4 + j]   (4 m16-tiles, 4 ksteps, 32 lanes x 4 regs)
    // B: [buf][(nt*4 + ks)*64  + lane*2 + j]   (8 n8-tiles,  4 ksteps, 32 lanes x 2 regs)
    __shared__ __align__(16) uint32_t As[2][2048];
    __shared__ __align__(16) uint32_t Bs[2][2048];

    const int t    = threadIdx.x;
    const int lane = t & 31;
    const int w    = t >> 5;
    const int wm   = w >> 2;      // 0..1 (m offset 32)
    const int wn   = w & 3;       // 0..3 (n offset 16)
    const int m0   = blockIdx.y * 64;
    const int n0   = blockIdx.x * 64;

    // staging indices: thread covers rows {srow, srow+32} x float4 col k4
    const int srow = t >> 3;      // 0..31
    const int k4   = t & 7;       // float4 index within BK=32
    const int ks_s = k4 >> 1;     // kstep 0..3
    const int jA   = (k4 & 1) * 2;  // A j contribution from k-half
    const int jB   = (k4 & 1);      // B j

    float acc[2][2][4];
    #pragma unroll
    for (int i = 0; i < 2; i++)
        #pragma unroll
        for (int j = 0; j < 2; j++)
            #pragma unroll
            for (int q = 0; q < 4; q++) acc[i][j][q] = 0.f;

    const float4 z4 = make_float4(0.f, 0.f, 0.f, 0.f);
    float4 ga[2], gb[2];

    #define TLOAD(kt)                                                          \
        { _Pragma("unroll")                                                    \
          for (int p = 0; p < 2; p++) {                                        \
            const int rr = p * 32 + srow;                                      \
            const int m = m0 + rr;                                             \
            ga[p] = (m < M) ? *(const float4*)(A + (size_t)m * K + (kt)*32 + k4*4) : z4; \
            gb[p] = *(const float4*)(Bm + (size_t)(n0 + rr) * K + (kt)*32 + k4*4);       \
          } }

    #define TSTORE(buf)                                                        \
        { _Pragma("unroll")                                                    \
          for (int p = 0; p < 2; p++) {                                        \
            const int rr = p * 32 + srow;                                      \
            const int mt = rr >> 4, rr16 = rr & 15;                            \
            const int lbA = (rr16 & 7) * 4;                                    \
            const int jjA = (rr16 >> 3) + jA;                                  \
            uint32_t* da = &As[buf][(mt*4 + ks_s)*128 + jjA];                  \
            da[(lbA+0)*4] = f2tf(ga[p].x); da[(lbA+1)*4] = f2tf(ga[p].y);      \
            da[(lbA+2)*4] = f2tf(ga[p].z); da[(lbA+3)*4] = f2tf(ga[p].w);      \
            const int nt = rr >> 3, nn8 = rr & 7;                              \
            uint32_t* db = &Bs[buf][(nt*4 + ks_s)*64 + jB];                    \
            db[(nn8*4+0)*2] = f2tf(gb[p].x); db[(nn8*4+1)*2] = f2tf(gb[p].y);  \
            db[(nn8*4+2)*2] = f2tf(gb[p].z); db[(nn8*4+3)*2] = f2tf(gb[p].w);  \
          } }

    TLOAD(0);
    TSTORE(0);
    __syncthreads();

    const int nkt = K >> 5;
    for (int kt = 0; kt < nkt; kt++) {
        const int cur = kt & 1;
        if (kt + 1 < nkt) TLOAD(kt + 1);
        #pragma unroll
        for (int ks = 0; ks < 4; ks++) {
            uint4 afr[2];
            uint2 bfr[2];
            #pragma unroll
            for (int i = 0; i < 2; i++)
                afr[i] = *(const uint4*)&As[cur][((wm*2 + i)*4 + ks)*128 + lane*4];
            #pragma unroll
            for (int j = 0; j < 2; j++)
                bfr[j] = *(const uint2*)&Bs[cur][((wn*2 + j)*4 + ks)*64 + lane*2];
            #pragma unroll
            for (int i = 0; i < 2; i++)
                #pragma unroll
                for (int j = 0; j < 2; j++)
                    mma8(acc[i][j], afr[i], bfr[j]);
        }
        if (kt + 1 < nkt) {
            TSTORE(cur ^ 1);
            __syncthreads();
        }
    }
    #undef TLOAD
    #undef TSTORE

    // epilogue: c0,c1 -> (row, 2c..2c+1); c2,c3 -> (row+8, ...)
    const int mr  = lane >> 2;
    const int nc  = (lane & 3) * 2;
    #pragma unroll
    for (int i = 0; i < 2; i++) {
        #pragma unroll
        for (int j = 0; j < 2; j++) {
            const int mrow = m0 + wm*32 + i*16 + mr;
            const int ncol = n0 + wn*16 + j*8 + nc;
            float2 bv = *(const float2*)(bias + ncol);
            float2 v0 = make_float2(acc[i][j][0] + bv.x, acc[i][j][1] + bv.y);
            float2 v1 = make_float2(acc[i][j][2] + bv.x, acc[i][j][3] + bv.y);
            if (EPI == 2) {
                if (mrow < M) {
                    float2 c0 = *(const float2*)(Cadd + (size_t)mrow * N + ncol);
                    v0.x += c0.x; v0.y += c0.y;
                }
                if (mrow + 8 < M) {
                    float2 c1 = *(const float2*)(Cadd + (size_t)(mrow + 8) * N + ncol);
                    v1.x += c1.x; v1.y += c1.y;
                }
            }
            if (mrow < M)     *(float2*)(C + (size_t)mrow * N + ncol) = v0;
            if (mrow + 8 < M) *(float2*)(C + (size_t)(mrow + 8) * N + ncol) = v1;
        }
    }
}

// ---------------- residual + layernorm (sums the 2 split-K planes + b2) ----------------
__global__ __launch_bounds__(256)
void ln_kernel(const float* __restrict__ g, const float* __restrict__ b,
               const float* __restrict__ b2)
{
    const int row = blockIdx.x;
    const int t = threadIdx.x;
    const int lane = t & 31, w = t >> 5;
    const float x = g_cat[(size_t)row * DMM + t];
    const float y = g_h2[(size_t)row * DMM + t]
                  + g_h2[(size_t)(RTOT + row) * DMM + t]
                  + b2[t] + x;

    __shared__ float s1[8], s2[8];
    __shared__ float s_mu, s_rs;
    float s = y, ss = y * y;
    #pragma unroll
    for (int o = 16; o; o >>= 1) {
        s  += __shfl_down_sync(0xffffffffu, s,  o);
        ss += __shfl_down_sync(0xffffffffu, ss, o);
    }
    if (lane == 0) { s1[w] = s; s2[w] = ss; }
    __syncthreads();
    if (t == 0) {
        float S = 0.f, SS = 0.f;
        #pragma unroll
        for (int i = 0; i < 8; i++) { S += s1[i]; SS += s2[i]; }
        const float mu = S / DMM;
        const float var = SS / DMM - mu * mu;
        s_mu = mu; s_rs = rsqrtf(var + 1e-5f);
    }
    __syncthreads();
    const float o = g[t] * (y - s_mu) * s_rs + b[t];
    if (row < NQ) g_qg[(size_t)row * DMM + t] = o;
    else          g_sse[(size_t)(row - NQ) * DMM + t] = o;
}

// ---------------- support mean + l2norm ----------------
__global__ __launch_bounds__(256)
void support_reduce()
{
    const int t = threadIdx.x;
    const int lane = t & 31, w = t >> 5;
    float s = 0.f;
    #pragma unroll
    for (int r = 0; r < FEWS; r++) s += g_sse[r * DMM + t];
    s *= (1.f / FEWS);
    g_sg[t] = s;

    __shared__ float s1[8];
    __shared__ float s_n;
    float p = s * s;
    #pragma unroll
    for (int o = 16; o; o >>= 1) p += __shfl_down_sync(0xffffffffu, p, o);
    if (lane == 0) s1[w] = p;
    __syncthreads();
    if (t == 0) {
        float S = 0.f;
        #pragma unroll
        for (int i = 0; i < 8; i++) S += s1[i];
        s_n = fmaxf(sqrtf(S), 1e-12f);
    }
    __syncthreads();
    g_sgn[t] = s / s_n;
}

// ---------------- LSTM step 0 on compacted gates ----------------
__global__ __launch_bounds__(256)
void e0_kernel()
{
    const int idx = blockIdx.x * 256 + threadIdx.x;   // NQ*256
    const int row = idx >> 8, j = idx & 255;
    const float* gr = g_GxC + (size_t)row * GC;
    const float ig = 1.f / (1.f + expf(-gr[j]));
    const float gg = tanhf(gr[512 + j]);
    const float c  = ig * gg;
    g_c0[idx] = c;
    const float og = 1.f / (1.f + expf(-gr[768 + j]));
    g_hr[idx] = g_qg[idx] + og * tanhf(c);
}

// ---------------- LSTM step 1 + l2norm + final dot ----------------
__global__ __launch_bounds__(256)
void final_kernel(float* __restrict__ out)
{
    const int row = blockIdx.x;
    const int t = threadIdx.x;
    const int lane = t & 31, w = t >> 5;
    const float* gr = g_gates + (size_t)row * GC;
    const float ig = 1.f / (1.f + expf(-gr[t]));
    const float fg = 1.f / (1.f + expf(-gr[256 + t]));
    const float gg = tanhf(gr[512 + t]);
    const float og = 1.f / (1.f + expf(-gr[768 + t]));
    const float c  = fg * g_c0[(size_t)row * DMM + t] + ig * gg;
    const float h  = g_qg[(size_t)row * DMM + t] + og * tanhf(c);

    float d = h * g_sgn[t];
    float n2 = h * h;
    __shared__ float sd[8], sn[8];
    #pragma unroll
    for (int o = 16; o; o >>= 1) {
        d  += __shfl_down_sync(0xffffffffu, d,  o);
        n2 += __shfl_down_sync(0xffffffffu, n2, o);
    }
    if (lane == 0) { sd[w] = d; sn[w] = n2; }
    __syncthreads();
    if (t == 0) {
        float DT = 0.f, NT = 0.f;
        #pragma unroll
        for (int i = 0; i < 8; i++) { DT += sd[i]; NT += sn[i]; }
        out[row] = DT / fmaxf(sqrtf(NT), 1e-12f);
    }
}

// ---------------- launch ----------------
extern "C" void kernel_launch(void* const* d_in, const int* in_sizes, int n_in,
                              void* d_out, int out_size)
{
    const int*   query   = (const int*)  d_in[0];
    const int*   support = (const int*)  d_in[1];
    const int*   qlc     = (const int*)  d_in[2];
    const int*   qrc     = (const int*)  d_in[4];
    const int*   slc     = (const int*)  d_in[6];
    const int*   src     = (const int*)  d_in[8];
    const float* emb     = (const float*)d_in[10];
    const float* gcnW    = (const float*)d_in[11];
    const float* gbias   = (const float*)d_in[12];
    const float* gb      = (const float*)d_in[13];
    const float* w1      = (const float*)d_in[14];
    const float* b1      = (const float*)d_in[15];
    const float* w2      = (const float*)d_in[16];
    const float* b2      = (const float*)d_in[17];
    const float* lng     = (const float*)d_in[18];
    const float* lnb     = (const float*)d_in[19];
    const float* Wih     = (const float*)d_in[20];
    const float* Whh     = (const float*)d_in[21];
    const float* bih     = (const float*)d_in[22];
    const float* bhh     = (const float*)d_in[23];
    float* out = (float*)d_out;

    float *p_cat, *p_h1, *p_h2, *p_qg, *p_WihC, *p_WhhC, *p_bsumC, *p_svec;
    float *p_GxC, *p_gates, *p_hr;
    cudaGetSymbolAddress((void**)&p_cat,   g_cat);
    cudaGetSymbolAddress((void**)&p_h1,    g_h1);
    cudaGetSymbolAddress((void**)&p_h2,    g_h2);
    cudaGetSymbolAddress((void**)&p_qg,    g_qg);
    cudaGetSymbolAddress((void**)&p_WihC,  g_WihC);
    cudaGetSymbolAddress((void**)&p_WhhC,  g_WhhC);
    cudaGetSymbolAddress((void**)&p_bsumC, g_bsumC);
    cudaGetSymbolAddress((void**)&p_svec,  g_svec);
    cudaGetSymbolAddress((void**)&p_GxC,   g_GxC);
    cudaGetSymbolAddress((void**)&p_gates, g_gates);
    cudaGetSymbolAddress((void**)&p_hr,    g_hr);

    compact_kernel<<<GC * DMM / 256, 256>>>(Wih, Whh, bih, bhh);
    neighbor_all<<<NBLK, 256>>>(emb, qlc, qrc, slc, src, query, support, gcnW, gbias, gb);

    // support encoder (batched query + support rows) — fp32
    sgemm_nt<1><<<dim3(DFF / 64, (RTOT + 63) / 64), 256>>>(p_cat, w1, p_h1, RTOT, DFF, DMM, b1, nullptr);
    sgemm_nt<3><<<dim3(DMM / 64, (RTOT + 63) / 64, 2), 256>>>(p_h1, w2, p_h2, RTOT, DMM, DFF, nullptr, nullptr);
    ln_kernel<<<RTOT, 256>>>(lng, lnb, b2);
    support_reduce<<<1, 256>>>();
    svec_kernel<<<GC / 8, 256>>>(Whh);

    // query encoder on compacted gate columns — tf32 tensor cores
    tgemm<0><<<dim3(GC / 64, NQ / 64), 256>>>(p_qg, p_WihC, p_GxC, NQ, GC, DMM, p_bsumC, nullptr);
    e0_kernel<<<NQ * DMM / 256, 256>>>();
    tgemm<2><<<dim3(GC / 64, NQ / 64), 256>>>(p_hr, p_WhhC, p_gates, NQ, GC, DMM, p_svec, p_GxC);
    final_kernel<<<NQ, 256>>>(out);
}

// round 6
// speedup vs baseline: 3.3258x; 1.0831x over previous
#include <cuda_runtime.h>
#include <math.h>
#include <stdint.h>

#define NQ    1024
#define FEWS  5
#define MCAND 200
#define KSEL  32
#define DD    128
#define DMM   256
#define DFF   512
#define HHH   512
#define GC    1024            // compacted gate columns (4 x 256)
#define RTOT  (NQ + FEWS)     // 1029
#define NBLK  (2*NQ + 2*FEWS) // 2058 neighbor tasks

// ---------------- workspace (device globals; no allocations) ----------------
__device__ float g_cat  [RTOT * DMM];
__device__ float g_h1   [RTOT * DFF];
__device__ float g_h2   [2 * RTOT * DMM];   // 2 split-K planes
__device__ float g_qg   [NQ   * DMM];
__device__ float g_sse  [FEWS * DMM];
__device__ float g_sg   [DMM];
__device__ float g_sgn  [DMM];
__device__ float g_WihC [GC * DMM];
__device__ float g_WhhC [GC * DMM];
__device__ float g_bsumC[GC];
__device__ float g_svec [GC];
__device__ float g_GxC  [NQ * GC];
__device__ float g_gates[NQ * GC];
__device__ float g_c0   [NQ * DMM];
__device__ float g_hr   [NQ * DMM];

__device__ __forceinline__ int orig_col(int r) { return ((r >> 8) << 9) + (r & 255); }

__device__ __forceinline__ uint32_t f2tf(float x) {
    uint32_t r;
    asm("cvt.rna.tf32.f32 %0, %1;" : "=r"(r) : "f"(x));
    return r;
}

__device__ __forceinline__ void mma8(float* c, const uint4& a, const uint2& b) {
    asm volatile(
        "mma.sync.aligned.m16n8k8.row.col.f32.tf32.tf32.f32 "
        "{%0,%1,%2,%3}, {%4,%5,%6,%7}, {%8,%9}, {%0,%1,%2,%3};"
        : "+f"(c[0]), "+f"(c[1]), "+f"(c[2]), "+f"(c[3])
        : "r"(a.x), "r"(a.y), "r"(a.z), "r"(a.w), "r"(b.x), "r"(b.y));
}

// ---------------- weight compaction: live gate columns only ----------------
__global__ __launch_bounds__(256)
void compact_kernel(const float* __restrict__ Wih, const float* __restrict__ Whh,
                    const float* __restrict__ bih, const float* __restrict__ bhh)
{
    const int idx = blockIdx.x * 256 + threadIdx.x;   // GC*DMM threads
    const int r = idx >> 8, c = idx & 255;
    const int o = orig_col(r);
    g_WihC[idx] = Wih[(size_t)o * DMM + c];
    g_WhhC[idx] = Whh[(size_t)o * HHH + c];
    if (c == 0) g_bsumC[r] = bih[o] + bhh[o];
}

// ---------------- svec[r] = dot(Whh[orig(r), 256:512], support_g) ----------------
__global__ __launch_bounds__(256)
void svec_kernel(const float* __restrict__ Whh)
{
    const int lane = threadIdx.x & 31;
    const int r = blockIdx.x * 8 + (threadIdx.x >> 5);
    const int o = orig_col(r);
    const float* wr = Whh + (size_t)o * HHH + DMM;
    float p = 0.f;
    #pragma unroll
    for (int c = lane; c < DMM; c += 32) p += wr[c] * g_sg[c];
    #pragma unroll
    for (int off = 16; off; off >>= 1) p += __shfl_down_sync(0xffffffffu, p, off);
    if (lane == 0) g_svec[r] = p;
}

// ---------------- neighbor encoder: all 2058 tasks in one launch ----------------
__global__ __launch_bounds__(256)
void neighbor_all(const float* __restrict__ emb,
                  const int* __restrict__ qlc, const int* __restrict__ qrc,
                  const int* __restrict__ slc, const int* __restrict__ src,
                  const int* __restrict__ query, const int* __restrict__ support,
                  const float* __restrict__ gcnW,
                  const float* __restrict__ gbias, const float* __restrict__ gb)
{
    const int b = blockIdx.x;
    const int t = threadIdx.x;
    const int lane = t & 31;
    const int w = t >> 5;

    const int* conn_row;
    int cid, out_row, coff;
    if (b < NQ)            { conn_row = qlc + (size_t)b * MCAND * 2;            cid = query[b * 2 + 0];           out_row = b;                 coff = 0;  }
    else if (b < 2 * NQ)   { int rb = b - NQ;   conn_row = qrc + (size_t)rb * MCAND * 2; cid = query[rb * 2 + 1]; out_row = rb;                coff = DD; }
    else if (b < 2*NQ+FEWS){ int rb = b - 2*NQ; conn_row = slc + (size_t)rb * MCAND * 2; cid = support[rb*2 + 0]; out_row = NQ + rb;           coff = 0;  }
    else                   { int rb = b - 2*NQ - FEWS; conn_row = src + (size_t)rb * MCAND * 2; cid = support[rb*2 + 1]; out_row = NQ + rb;    coff = DD; }

    __shared__ __align__(16) float s_center[DD];
    __shared__ float s_sim [MCAND];
    __shared__ int   s_ridx[MCAND];
    __shared__ int   s_eidx[MCAND];
    __shared__ int   s_selr[KSEL];
    __shared__ int   s_sele[KSEL];
    __shared__ float s_mcat[DMM];
    __shared__ float s_red[8];
    __shared__ float s_cn;

    for (int n = t; n < MCAND; n += 256) {
        s_ridx[n] = conn_row[n * 2 + 0];
        s_eidx[n] = conn_row[n * 2 + 1];
    }
    float cv = 0.f;
    if (t < DD) { cv = emb[(size_t)cid * DD + t]; s_center[t] = cv; }

    float p = cv * cv;
    #pragma unroll
    for (int o = 16; o; o >>= 1) p += __shfl_down_sync(0xffffffffu, p, o);
    if (lane == 0) s_red[w] = p;
    __syncthreads();
    if (t == 0) {
        float s = 0.f;
        #pragma unroll
        for (int i = 0; i < 8; i++) s += s_red[i];
        s_cn = sqrtf(s);
    }
    __syncthreads();
    const float cn = s_cn;

    // cosine sims: warp handles 2 neighbors per iteration (2x MLP + ILP)
    const float4 c4 = *(const float4*)(s_center + lane * 4);
    for (int n = w; n < MCAND; n += 16) {
        const int n1 = n + 8;
        const bool h1 = n1 < MCAND;
        const float4 e0 = *(const float4*)(emb + (size_t)s_eidx[n] * DD + lane * 4);
        float4 e1 = e0;
        if (h1) e1 = *(const float4*)(emb + (size_t)s_eidx[n1] * DD + lane * 4);
        float num0 = e0.x*c4.x + e0.y*c4.y + e0.z*c4.z + e0.w*c4.w;
        float nn0  = e0.x*e0.x + e0.y*e0.y + e0.z*e0.z + e0.w*e0.w;
        float num1 = e1.x*c4.x + e1.y*c4.y + e1.z*c4.z + e1.w*c4.w;
        float nn1  = e1.x*e1.x + e1.y*e1.y + e1.z*e1.z + e1.w*e1.w;
        #pragma unroll
        for (int o = 16; o; o >>= 1) {
            num0 += __shfl_down_sync(0xffffffffu, num0, o);
            nn0  += __shfl_down_sync(0xffffffffu, nn0,  o);
            num1 += __shfl_down_sync(0xffffffffu, num1, o);
            nn1  += __shfl_down_sync(0xffffffffu, nn1,  o);
        }
        if (lane == 0) {
            s_sim[n] = num0 / fmaxf(cn * sqrtf(nn0), 1e-8f);
            if (h1) s_sim[n1] = num1 / fmaxf(cn * sqrtf(nn1), 1e-8f);
        }
    }
    __syncthreads();

    // top-K with jax.lax.top_k tie-break (lower index wins); rank is a permutation
    if (t < MCAND) {
        const float v = s_sim[t];
        int r = 0;
        for (int i = 0; i < MCAND; i++) {
            const float u = s_sim[i];
            r += (u > v) || (u == v && i < t);
        }
        if (r < KSEL) { s_selr[r] = s_ridx[t]; s_sele[r] = s_eidx[t]; }
    }
    __syncthreads();

    // mean of selected [rel ; ent]
    {
        float acc = 0.f;
        if (t < DD) {
            #pragma unroll 8
            for (int k = 0; k < KSEL; k++) acc += emb[(size_t)s_selr[k] * DD + t];
        } else {
            const int d = t - DD;
            #pragma unroll 8
            for (int k = 0; k < KSEL; k++) acc += emb[(size_t)s_sele[k] * DD + d];
        }
        s_mcat[t] = acc * (1.f / KSEL);
    }
    __syncthreads();

    // GEMV 256 -> 128 (+biases, tanh)
    for (int dd = 0; dd < 16; dd++) {
        const int d = w * 16 + dd;
        const float* wr = gcnW + (size_t)d * DMM;
        float pp = 0.f;
        #pragma unroll
        for (int c = lane; c < DMM; c += 32) pp += wr[c] * s_mcat[c];
        #pragma unroll
        for (int o = 16; o; o >>= 1) pp += __shfl_down_sync(0xffffffffu, pp, o);
        if (lane == 0)
            g_cat[(size_t)out_row * DMM + coff + d] = tanhf(pp + gbias[d] + gb[d]);
    }
}

// ---------------- tf32 tensor-core GEMM: C[M,N] = A[M,K] @ B[N,K]^T ----------------
// Block tile 64x64, BK=32, 8 warps (2m x 4n), warp tile 32x16 via m16n8k8 mma.
// smem holds tiles in FRAGMENT order: A frag = LDS.128/thread, B frag = LDS.64.
// gridDim.z = split-K; plane z writes C + z*M*N (EPI 3).
// EPI: 0 = +bias[n], 1 = relu(+bias[n]), 2 = +Cadd[m,n]+bias[n], 3 = raw
template <int EPI>
__global__ __launch_bounds__(256)
void tgemm(const float* __restrict__ A, const float* __restrict__ Bm,
           float* __restrict__ C, int M, int N, int K,
           const float* __restrict__ bias, const float* __restrict__ Cadd)
{
    __shared__ __align__(16) uint32_t As[2][2048];
    __shared__ __align__(16) uint32_t Bs[2][2048];

    const int t    = threadIdx.x;
    const int lane = t & 31;
    const int w    = t >> 5;
    const int wm   = w >> 2;      // 0..1 (m offset 32)
    const int wn   = w & 3;       // 0..3 (n offset 16)
    const int m0   = blockIdx.y * 64;
    const int n0   = blockIdx.x * 64;
    const int ksz  = K / gridDim.z;
    const int kb   = blockIdx.z * ksz;

    const int srow = t >> 3;      // 0..31
    const int k4   = t & 7;       // float4 index within BK=32
    const int ks_s = k4 >> 1;     // kstep 0..3
    const int jA   = (k4 & 1) * 2;
    const int jB   = (k4 & 1);

    float acc[2][2][4];
    #pragma unroll
    for (int i = 0; i < 2; i++)
        #pragma unroll
        for (int j = 0; j < 2; j++)
            #pragma unroll
            for (int q = 0; q < 4; q++) acc[i][j][q] = 0.f;

    const float4 z4 = make_float4(0.f, 0.f, 0.f, 0.f);
    float4 ga[2], gb[2];

    #define TLOAD(kt)                                                          \
        { _Pragma("unroll")                                                    \
          for (int p = 0; p < 2; p++) {                                        \
            const int rr = p * 32 + srow;                                      \
            const int m = m0 + rr;                                             \
            ga[p] = (m < M) ? *(const float4*)(A + (size_t)m * K + kb + (kt)*32 + k4*4) : z4; \
            gb[p] = *(const float4*)(Bm + (size_t)(n0 + rr) * K + kb + (kt)*32 + k4*4);       \
          } }

    #define TSTORE(buf)                                                        \
        { _Pragma("unroll")                                                    \
          for (int p = 0; p < 2; p++) {                                        \
            const int rr = p * 32 + srow;                                      \
            const int mt = rr >> 4, rr16 = rr & 15;                            \
            const int lbA = (rr16 & 7) * 4;                                    \
            const int jjA = (rr16 >> 3) + jA;                                  \
            uint32_t* da = &As[buf][(mt*4 + ks_s)*128 + jjA];                  \
            da[(lbA+0)*4] = f2tf(ga[p].x); da[(lbA+1)*4] = f2tf(ga[p].y);      \
            da[(lbA+2)*4] = f2tf(ga[p].z); da[(lbA+3)*4] = f2tf(ga[p].w);      \
            const int nt = rr >> 3, nn8 = rr & 7;                              \
            uint32_t* db = &Bs[buf][(nt*4 + ks_s)*64 + jB];                    \
            db[(nn8*4+0)*2] = f2tf(gb[p].x); db[(nn8*4+1)*2] = f2tf(gb[p].y);  \
            db[(nn8*4+2)*2] = f2tf(gb[p].z); db[(nn8*4+3)*2] = f2tf(gb[p].w);  \
          } }

    TLOAD(0);
    TSTORE(0);
    __syncthreads();

    const int nkt = ksz >> 5;
    for (int kt = 0; kt < nkt; kt++) {
        const int cur = kt & 1;
        if (kt + 1 < nkt) TLOAD(kt + 1);
        #pragma unroll
        for (int ks = 0; ks < 4; ks++) {
            uint4 afr[2];
            uint2 bfr[2];
            #pragma unroll
            for (int i = 0; i < 2; i++)
                afr[i] = *(const uint4*)&As[cur][((wm*2 + i)*4 + ks)*128 + lane*4];
            #pragma unroll
            for (int j = 0; j < 2; j++)
                bfr[j] = *(const uint2*)&Bs[cur][((wn*2 + j)*4 + ks)*64 + lane*2];
            #pragma unroll
            for (int i = 0; i < 2; i++)
                #pragma unroll
                for (int j = 0; j < 2; j++)
                    mma8(acc[i][j], afr[i], bfr[j]);
        }
        if (kt + 1 < nkt) {
            TSTORE(cur ^ 1);
            __syncthreads();
        }
    }
    #undef TLOAD
    #undef TSTORE

    C += (size_t)blockIdx.z * M * N;
    const int mr  = lane >> 2;
    const int nc  = (lane & 3) * 2;
    #pragma unroll
    for (int i = 0; i < 2; i++) {
        #pragma unroll
        for (int j = 0; j < 2; j++) {
            const int mrow = m0 + wm*32 + i*16 + mr;
            const int ncol = n0 + wn*16 + j*8 + nc;
            float2 bv = make_float2(0.f, 0.f);
            if (EPI != 3) bv = *(const float2*)(bias + ncol);
            float2 v0 = make_float2(acc[i][j][0] + bv.x, acc[i][j][1] + bv.y);
            float2 v1 = make_float2(acc[i][j][2] + bv.x, acc[i][j][3] + bv.y);
            if (EPI == 1) {
                v0.x = fmaxf(v0.x, 0.f); v0.y = fmaxf(v0.y, 0.f);
                v1.x = fmaxf(v1.x, 0.f); v1.y = fmaxf(v1.y, 0.f);
            }
            if (EPI == 2) {
                if (mrow < M) {
                    float2 c0 = *(const float2*)(Cadd + (size_t)mrow * N + ncol);
                    v0.x += c0.x; v0.y += c0.y;
                }
                if (mrow + 8 < M) {
                    float2 c1 = *(const float2*)(Cadd + (size_t)(mrow + 8) * N + ncol);
                    v1.x += c1.x; v1.y += c1.y;
                }
            }
            if (mrow < M)     *(float2*)(C + (size_t)mrow * N + ncol) = v0;
            if (mrow + 8 < M) *(float2*)(C + (size_t)(mrow + 8) * N + ncol) = v1;
        }
    }
}

// ---------------- residual + layernorm (sums the 2 split-K planes + b2) ----------------
__global__ __launch_bounds__(256)
void ln_kernel(const float* __restrict__ g, const float* __restrict__ b,
               const float* __restrict__ b2)
{
    const int row = blockIdx.x;
    const int t = threadIdx.x;
    const int lane = t & 31, w = t >> 5;
    const float x = g_cat[(size_t)row * DMM + t];
    const float y = g_h2[(size_t)row * DMM + t]
                  + g_h2[(size_t)(RTOT + row) * DMM + t]
                  + b2[t] + x;

    __shared__ float s1[8], s2[8];
    __shared__ float s_mu, s_rs;
    float s = y, ss = y * y;
    #pragma unroll
    for (int o = 16; o; o >>= 1) {
        s  += __shfl_down_sync(0xffffffffu, s,  o);
        ss += __shfl_down_sync(0xffffffffu, ss, o);
    }
    if (lane == 0) { s1[w] = s; s2[w] = ss; }
    __syncthreads();
    if (t == 0) {
        float S = 0.f, SS = 0.f;
        #pragma unroll
        for (int i = 0; i < 8; i++) { S += s1[i]; SS += s2[i]; }
        const float mu = S / DMM;
        const float var = SS / DMM - mu * mu;
        s_mu = mu; s_rs = rsqrtf(var + 1e-5f);
    }
    __syncthreads();
    const float o = g[t] * (y - s_mu) * s_rs + b[t];
    if (row < NQ) g_qg[(size_t)row * DMM + t] = o;
    else          g_sse[(size_t)(row - NQ) * DMM + t] = o;
}

// ---------------- support mean + l2norm ----------------
__global__ __launch_bounds__(256)
void support_reduce()
{
    const int t = threadIdx.x;
    const int lane = t & 31, w = t >> 5;
    float s = 0.f;
    #pragma unroll
    for (int r = 0; r < FEWS; r++) s += g_sse[r * DMM + t];
    s *= (1.f / FEWS);
    g_sg[t] = s;

    __shared__ float s1[8];
    __shared__ float s_n;
    float p = s * s;
    #pragma unroll
    for (int o = 16; o; o >>= 1) p += __shfl_down_sync(0xffffffffu, p, o);
    if (lane == 0) s1[w] = p;
    __syncthreads();
    if (t == 0) {
        float S = 0.f;
        #pragma unroll
        for (int i = 0; i < 8; i++) S += s1[i];
        s_n = fmaxf(sqrtf(S), 1e-12f);
    }
    __syncthreads();
    g_sgn[t] = s / s_n;
}

// ---------------- LSTM step 0 on compacted gates ----------------
__global__ __launch_bounds__(256)
void e0_kernel()
{
    const int idx = blockIdx.x * 256 + threadIdx.x;   // NQ*256
    const int row = idx >> 8, j = idx & 255;
    const float* gr = g_GxC + (size_t)row * GC;
    const float ig = 1.f / (1.f + expf(-gr[j]));
    const float gg = tanhf(gr[512 + j]);
    const float c  = ig * gg;
    g_c0[idx] = c;
    const float og = 1.f / (1.f + expf(-gr[768 + j]));
    g_hr[idx] = g_qg[idx] + og * tanhf(c);
}

// ---------------- LSTM step 1 + l2norm + final dot ----------------
__global__ __launch_bounds__(256)
void final_kernel(float* __restrict__ out)
{
    const int row = blockIdx.x;
    const int t = threadIdx.x;
    const int lane = t & 31, w = t >> 5;
    const float* gr = g_gates + (size_t)row * GC;
    const float ig = 1.f / (1.f + expf(-gr[t]));
    const float fg = 1.f / (1.f + expf(-gr[256 + t]));
    const float gg = tanhf(gr[512 + t]);
    const float og = 1.f / (1.f + expf(-gr[768 + t]));
    const float c  = fg * g_c0[(size_t)row * DMM + t] + ig * gg;
    const float h  = g_qg[(size_t)row * DMM + t] + og * tanhf(c);

    float d = h * g_sgn[t];
    float n2 = h * h;
    __shared__ float sd[8], sn[8];
    #pragma unroll
    for (int o = 16; o; o >>= 1) {
        d  += __shfl_down_sync(0xffffffffu, d,  o);
        n2 += __shfl_down_sync(0xffffffffu, n2, o);
    }
    if (lane == 0) { sd[w] = d; sn[w] = n2; }
    __syncthreads();
    if (t == 0) {
        float DT = 0.f, NT = 0.f;
        #pragma unroll
        for (int i = 0; i < 8; i++) { DT += sd[i]; NT += sn[i]; }
        out[row] = DT / fmaxf(sqrtf(NT), 1e-12f);
    }
}

// ---------------- launch ----------------
extern "C" void kernel_launch(void* const* d_in, const int* in_sizes, int n_in,
                              void* d_out, int out_size)
{
    const int*   query   = (const int*)  d_in[0];
    const int*   support = (const int*)  d_in[1];
    const int*   qlc     = (const int*)  d_in[2];
    const int*   qrc     = (const int*)  d_in[4];
    const int*   slc     = (const int*)  d_in[6];
    const int*   src     = (const int*)  d_in[8];
    const float* emb     = (const float*)d_in[10];
    const float* gcnW    = (const float*)d_in[11];
    const float* gbias   = (const float*)d_in[12];
    const float* gb      = (const float*)d_in[13];
    const float* w1      = (const float*)d_in[14];
    const float* b1      = (const float*)d_in[15];
    const float* w2      = (const float*)d_in[16];
    const float* b2      = (const float*)d_in[17];
    const float* lng     = (const float*)d_in[18];
    const float* lnb     = (const float*)d_in[19];
    const float* Wih     = (const float*)d_in[20];
    const float* Whh     = (const float*)d_in[21];
    const float* bih     = (const float*)d_in[22];
    const float* bhh     = (const float*)d_in[23];
    float* out = (float*)d_out;

    float *p_cat, *p_h1, *p_h2, *p_qg, *p_WihC, *p_WhhC, *p_bsumC, *p_svec;
    float *p_GxC, *p_gates, *p_hr;
    cudaGetSymbolAddress((void**)&p_cat,   g_cat);
    cudaGetSymbolAddress((void**)&p_h1,    g_h1);
    cudaGetSymbolAddress((void**)&p_h2,    g_h2);
    cudaGetSymbolAddress((void**)&p_qg,    g_qg);
    cudaGetSymbolAddress((void**)&p_WihC,  g_WihC);
    cudaGetSymbolAddress((void**)&p_WhhC,  g_WhhC);
    cudaGetSymbolAddress((void**)&p_bsumC, g_bsumC);
    cudaGetSymbolAddress((void**)&p_svec,  g_svec);
    cudaGetSymbolAddress((void**)&p_GxC,   g_GxC);
    cudaGetSymbolAddress((void**)&p_gates, g_gates);
    cudaGetSymbolAddress((void**)&p_hr,    g_hr);

    compact_kernel<<<GC * DMM / 256, 256>>>(Wih, Whh, bih, bhh);
    neighbor_all<<<NBLK, 256>>>(emb, qlc, qrc, slc, src, query, support, gcnW, gbias, gb);

    // support encoder (batched query + support rows) — tf32
    tgemm<1><<<dim3(DFF / 64, (RTOT + 63) / 64), 256>>>(p_cat, w1, p_h1, RTOT, DFF, DMM, b1, nullptr);
    tgemm<3><<<dim3(DMM / 64, (RTOT + 63) / 64, 2), 256>>>(p_h1, w2, p_h2, RTOT, DMM, DFF, nullptr, nullptr);
    ln_kernel<<<RTOT, 256>>>(lng, lnb, b2);
    support_reduce<<<1, 256>>>();
    svec_kernel<<<GC / 8, 256>>>(Whh);

    // query encoder on compacted gate columns — tf32
    tgemm<0><<<dim3(GC / 64, NQ / 64), 256>>>(p_qg, p_WihC, p_GxC, NQ, GC, DMM, p_bsumC, nullptr);
    e0_kernel<<<NQ * DMM / 256, 256>>>();
    tgemm<2><<<dim3(GC / 64, NQ / 64), 256>>>(p_hr, p_WhhC, p_gates, NQ, GC, DMM, p_svec, p_GxC);
    final_kernel<<<NQ, 256>>>(out);
}

// round 7
// speedup vs baseline: 3.6373x; 1.0937x over previous
#include <cuda_runtime.h>
#include <math.h>
#include <stdint.h>

#define NQ    1024
#define FEWS  5
#define MCAND 200
#define KSEL  32
#define DD    128
#define DMM   256
#define DFF   512
#define HHH   512
#define GC    1024            // compacted gate columns (4 x 256)
#define RTOT  (NQ + FEWS)     // 1029
#define NBLK  (2*NQ + 2*FEWS) // 2058 neighbor tasks

// ---------------- workspace (device globals; no allocations) ----------------
__device__ float g_mcat [NBLK * DMM];       // per-task K-mean [rel;ent]
__device__ float g_cat  [RTOT * DMM];
__device__ float g_h1   [RTOT * DFF];
__device__ float g_h2   [2 * RTOT * DMM];   // 2 split-K planes
__device__ float g_qg   [NQ   * DMM];
__device__ float g_sse  [FEWS * DMM];
__device__ float g_sg   [DMM];
__device__ float g_sgn  [DMM];
__device__ float g_WihC [GC * DMM];
__device__ float g_WhhC [GC * DMM];
__device__ float g_bsumC[GC];
__device__ float g_svec [GC];
__device__ float g_GxC  [NQ * GC];
__device__ float g_gates[NQ * GC];
__device__ float g_c0   [NQ * DMM];
__device__ float g_hr   [NQ * DMM];

__device__ __forceinline__ int orig_col(int r) { return ((r >> 8) << 9) + (r & 255); }

__device__ __forceinline__ uint32_t f2tf(float x) {
    uint32_t r;
    asm("cvt.rna.tf32.f32 %0, %1;" : "=r"(r) : "f"(x));
    return r;
}

__device__ __forceinline__ void mma8(float* c, const uint4& a, const uint2& b) {
    asm volatile(
        "mma.sync.aligned.m16n8k8.row.col.f32.tf32.tf32.f32 "
        "{%0,%1,%2,%3}, {%4,%5,%6,%7}, {%8,%9}, {%0,%1,%2,%3};"
        : "+f"(c[0]), "+f"(c[1]), "+f"(c[2]), "+f"(c[3])
        : "r"(a.x), "r"(a.y), "r"(a.z), "r"(a.w), "r"(b.x), "r"(b.y));
}

// ---------------- weight compaction: live gate columns only ----------------
__global__ __launch_bounds__(256)
void compact_kernel(const float* __restrict__ Wih, const float* __restrict__ Whh,
                    const float* __restrict__ bih, const float* __restrict__ bhh)
{
    const int idx = blockIdx.x * 256 + threadIdx.x;   // GC*DMM threads
    const int r = idx >> 8, c = idx & 255;
    const int o = orig_col(r);
    g_WihC[idx] = Wih[(size_t)o * DMM + c];
    g_WhhC[idx] = Whh[(size_t)o * HHH + c];
    if (c == 0) g_bsumC[r] = bih[o] + bhh[o];
}

// ---------------- svec[r] = dot(Whh[orig(r), 256:512], support_g) ----------------
__global__ __launch_bounds__(256)
void svec_kernel(const float* __restrict__ Whh)
{
    const int lane = threadIdx.x & 31;
    const int r = blockIdx.x * 8 + (threadIdx.x >> 5);
    const int o = orig_col(r);
    const float* wr = Whh + (size_t)o * HHH + DMM;
    float p = 0.f;
    #pragma unroll
    for (int c = lane; c < DMM; c += 32) p += wr[c] * g_sg[c];
    #pragma unroll
    for (int off = 16; off; off >>= 1) p += __shfl_down_sync(0xffffffffu, p, off);
    if (lane == 0) g_svec[r] = p;
}

// ---------------- neighbor encoder: sims + top-K + mean only ----------------
__global__ __launch_bounds__(256)
void neighbor_all(const float* __restrict__ emb,
                  const int* __restrict__ qlc, const int* __restrict__ qrc,
                  const int* __restrict__ slc, const int* __restrict__ src,
                  const int* __restrict__ query, const int* __restrict__ support)
{
    const int b = blockIdx.x;
    const int t = threadIdx.x;
    const int lane = t & 31;
    const int w = t >> 5;

    // task index tt: left tasks [0,1029), right tasks [1029, 2058)
    const int* conn_row;
    int cid, tt;
    if (b < NQ)            { conn_row = qlc + (size_t)b * MCAND * 2;                 cid = query[b * 2 + 0];   tt = b; }
    else if (b < 2 * NQ)   { int rb = b - NQ;        conn_row = qrc + (size_t)rb * MCAND * 2; cid = query[rb * 2 + 1];   tt = RTOT + rb; }
    else if (b < 2*NQ+FEWS){ int rb = b - 2*NQ;      conn_row = slc + (size_t)rb * MCAND * 2; cid = support[rb*2 + 0];   tt = NQ + rb; }
    else                   { int rb = b - 2*NQ-FEWS; conn_row = src + (size_t)rb * MCAND * 2; cid = support[rb*2 + 1];   tt = RTOT + NQ + rb; }

    __shared__ __align__(16) float s_center[DD];
    __shared__ float s_sim [MCAND];
    __shared__ int   s_ridx[MCAND];
    __shared__ int   s_eidx[MCAND];
    __shared__ int   s_selr[KSEL];
    __shared__ int   s_sele[KSEL];
    __shared__ float s_red[8];
    __shared__ float s_cn;

    for (int n = t; n < MCAND; n += 256) {
        s_ridx[n] = conn_row[n * 2 + 0];
        s_eidx[n] = conn_row[n * 2 + 1];
    }
    float cv = 0.f;
    if (t < DD) { cv = emb[(size_t)cid * DD + t]; s_center[t] = cv; }

    float p = cv * cv;
    #pragma unroll
    for (int o = 16; o; o >>= 1) p += __shfl_down_sync(0xffffffffu, p, o);
    if (lane == 0) s_red[w] = p;
    __syncthreads();
    if (t == 0) {
        float s = 0.f;
        #pragma unroll
        for (int i = 0; i < 8; i++) s += s_red[i];
        s_cn = sqrtf(s);
    }
    __syncthreads();
    const float cn = s_cn;

    // cosine sims: warp handles 2 neighbors per iteration (2x MLP + ILP)
    const float4 c4 = *(const float4*)(s_center + lane * 4);
    for (int n = w; n < MCAND; n += 16) {
        const int n1 = n + 8;
        const bool h1 = n1 < MCAND;
        const float4 e0 = *(const float4*)(emb + (size_t)s_eidx[n] * DD + lane * 4);
        float4 e1 = e0;
        if (h1) e1 = *(const float4*)(emb + (size_t)s_eidx[n1] * DD + lane * 4);
        float num0 = e0.x*c4.x + e0.y*c4.y + e0.z*c4.z + e0.w*c4.w;
        float nn0  = e0.x*e0.x + e0.y*e0.y + e0.z*e0.z + e0.w*e0.w;
        float num1 = e1.x*c4.x + e1.y*c4.y + e1.z*c4.z + e1.w*c4.w;
        float nn1  = e1.x*e1.x + e1.y*e1.y + e1.z*e1.z + e1.w*e1.w;
        #pragma unroll
        for (int o = 16; o; o >>= 1) {
            num0 += __shfl_down_sync(0xffffffffu, num0, o);
            nn0  += __shfl_down_sync(0xffffffffu, nn0,  o);
            num1 += __shfl_down_sync(0xffffffffu, num1, o);
            nn1  += __shfl_down_sync(0xffffffffu, nn1,  o);
        }
        if (lane == 0) {
            s_sim[n] = num0 / fmaxf(cn * sqrtf(nn0), 1e-8f);
            if (h1) s_sim[n1] = num1 / fmaxf(cn * sqrtf(nn1), 1e-8f);
        }
    }
    __syncthreads();

    // top-K with jax.lax.top_k tie-break (lower index wins); rank is a permutation
    if (t < MCAND) {
        const float v = s_sim[t];
        int r = 0;
        for (int i = 0; i < MCAND; i++) {
            const float u = s_sim[i];
            r += (u > v) || (u == v && i < t);
        }
        if (r < KSEL) { s_selr[r] = s_ridx[t]; s_sele[r] = s_eidx[t]; }
    }
    __syncthreads();

    // mean of selected [rel ; ent] -> g_mcat[tt]
    {
        float acc = 0.f;
        if (t < DD) {
            #pragma unroll 8
            for (int k = 0; k < KSEL; k++) acc += emb[(size_t)s_selr[k] * DD + t];
        } else {
            const int d = t - DD;
            #pragma unroll 8
            for (int k = 0; k < KSEL; k++) acc += emb[(size_t)s_sele[k] * DD + d];
        }
        g_mcat[(size_t)tt * DMM + t] = acc * (1.f / KSEL);
    }
}

// ---------------- tf32 tensor-core GEMM: C[M,N] = A[M,K] @ B[N,K]^T ----------------
// Block tile 64x64, BK=32, 8 warps (2m x 4n), warp tile 32x16 via m16n8k8 mma.
// smem in FRAGMENT order: A frag = LDS.128/thread, B frag = LDS.64.
// gridDim.z = split-K; plane z writes C + z*M*N (EPI 3).
// EPI: 0 = +bias[n], 1 = relu(+bias[n]), 2 = +Cadd[m,n]+bias[n], 3 = raw,
//      4 = tanh(+bias[n]+Cadd[n]) scattered to g_cat (gcn epilogue; N=128, M=2058)
template <int EPI>
__global__ __launch_bounds__(256)
void tgemm(const float* __restrict__ A, const float* __restrict__ Bm,
           float* __restrict__ C, int M, int N, int K,
           const float* __restrict__ bias, const float* __restrict__ Cadd)
{
    __shared__ __align__(16) uint32_t As[2][2048];
    __shared__ __align__(16) uint32_t Bs[2][2048];

    const int t    = threadIdx.x;
    const int lane = t & 31;
    const int w    = t >> 5;
    const int wm   = w >> 2;      // 0..1 (m offset 32)
    const int wn   = w & 3;       // 0..3 (n offset 16)
    const int m0   = blockIdx.y * 64;
    const int n0   = blockIdx.x * 64;
    const int ksz  = K / gridDim.z;
    const int kb   = blockIdx.z * ksz;

    const int srow = t >> 3;      // 0..31
    const int k4   = t & 7;       // float4 index within BK=32
    const int ks_s = k4 >> 1;     // kstep 0..3
    const int jA   = (k4 & 1) * 2;
    const int jB   = (k4 & 1);

    float acc[2][2][4];
    #pragma unroll
    for (int i = 0; i < 2; i++)
        #pragma unroll
        for (int j = 0; j < 2; j++)
            #pragma unroll
            for (int q = 0; q < 4; q++) acc[i][j][q] = 0.f;

    const float4 z4 = make_float4(0.f, 0.f, 0.f, 0.f);
    float4 ga[2], gb[2];

    #define TLOAD(kt)                                                          \
        { _Pragma("unroll")                                                    \
          for (int p = 0; p < 2; p++) {                                        \
            const int rr = p * 32 + srow;                                      \
            const int m = m0 + rr;                                             \
            ga[p] = (m < M) ? *(const float4*)(A + (size_t)m * K + kb + (kt)*32 + k4*4) : z4; \
            gb[p] = *(const float4*)(Bm + (size_t)(n0 + rr) * K + kb + (kt)*32 + k4*4);       \
          } }

    #define TSTORE(buf)                                                        \
        { _Pragma("unroll")                                                    \
          for (int p = 0; p < 2; p++) {                                        \
            const int rr = p * 32 + srow;                                      \
            const int mt = rr >> 4, rr16 = rr & 15;                            \
            const int lbA = (rr16 & 7) * 4;                                    \
            const int jjA = (rr16 >> 3) + jA;                                  \
            uint32_t* da = &As[buf][(mt*4 + ks_s)*128 + jjA];                  \
            da[(lbA+0)*4] = f2tf(ga[p].x); da[(lbA+1)*4] = f2tf(ga[p].y);      \
            da[(lbA+2)*4] = f2tf(ga[p].z); da[(lbA+3)*4] = f2tf(ga[p].w);      \
            const int nt = rr >> 3, nn8 = rr & 7;                              \
            uint32_t* db = &Bs[buf][(nt*4 + ks_s)*64 + jB];                    \
            db[(nn8*4+0)*2] = f2tf(gb[p].x); db[(nn8*4+1)*2] = f2tf(gb[p].y);  \
            db[(nn8*4+2)*2] = f2tf(gb[p].z); db[(nn8*4+3)*2] = f2tf(gb[p].w);  \
          } }

    TLOAD(0);
    TSTORE(0);
    __syncthreads();

    const int nkt = ksz >> 5;
    for (int kt = 0; kt < nkt; kt++) {
        const int cur = kt & 1;
        if (kt + 1 < nkt) TLOAD(kt + 1);
        #pragma unroll
        for (int ks = 0; ks < 4; ks++) {
            uint4 afr[2];
            uint2 bfr[2];
            #pragma unroll
            for (int i = 0; i < 2; i++)
                afr[i] = *(const uint4*)&As[cur][((wm*2 + i)*4 + ks)*128 + lane*4];
            #pragma unroll
            for (int j = 0; j < 2; j++)
                bfr[j] = *(const uint2*)&Bs[cur][((wn*2 + j)*4 + ks)*64 + lane*2];
            #pragma unroll
            for (int i = 0; i < 2; i++)
                #pragma unroll
                for (int j = 0; j < 2; j++)
                    mma8(acc[i][j], afr[i], bfr[j]);
        }
        if (kt + 1 < nkt) {
            TSTORE(cur ^ 1);
            __syncthreads();
        }
    }
    #undef TLOAD
    #undef TSTORE

    C += (size_t)blockIdx.z * M * N;
    const int mr  = lane >> 2;
    const int nc  = (lane & 3) * 2;
    #pragma unroll
    for (int i = 0; i < 2; i++) {
        #pragma unroll
        for (int j = 0; j < 2; j++) {
            const int mrow = m0 + wm*32 + i*16 + mr;
            const int ncol = n0 + wn*16 + j*8 + nc;
            if (EPI == 4) {
                // scatter: task m -> g_cat[row][coff + n], tanh(acc + gbias + gb)
                const float2 bb = *(const float2*)(bias + ncol);
                const float2 cc = *(const float2*)(Cadd + ncol);
                #pragma unroll
                for (int q = 0; q < 2; q++) {
                    const int mm = mrow + q * 8;
                    if (mm < M) {
                        const int r    = (mm < RTOT) ? mm : mm - RTOT;
                        const int coff = (mm < RTOT) ? 0 : DD;
                        float2 v;
                        v.x = tanhf(acc[i][j][q*2+0] + bb.x + cc.x);
                        v.y = tanhf(acc[i][j][q*2+1] + bb.y + cc.y);
                        *(float2*)(g_cat + (size_t)r * DMM + coff + ncol) = v;
                    }
                }
                continue;
            }
            float2 bv = make_float2(0.f, 0.f);
            if (EPI != 3) bv = *(const float2*)(bias + ncol);
            float2 v0 = make_float2(acc[i][j][0] + bv.x, acc[i][j][1] + bv.y);
            float2 v1 = make_float2(acc[i][j][2] + bv.x, acc[i][j][3] + bv.y);
            if (EPI == 1) {
                v0.x = fmaxf(v0.x, 0.f); v0.y = fmaxf(v0.y, 0.f);
                v1.x = fmaxf(v1.x, 0.f); v1.y = fmaxf(v1.y, 0.f);
            }
            if (EPI == 2) {
                if (mrow < M) {
                    float2 c0 = *(const float2*)(Cadd + (size_t)mrow * N + ncol);
                    v0.x += c0.x; v0.y += c0.y;
                }
                if (mrow + 8 < M) {
                    float2 c1 = *(const float2*)(Cadd + (size_t)(mrow + 8) * N + ncol);
                    v1.x += c1.x; v1.y += c1.y;
                }
            }
            if (mrow < M)     *(float2*)(C + (size_t)mrow * N + ncol) = v0;
            if (mrow + 8 < M) *(float2*)(C + (size_t)(mrow + 8) * N + ncol) = v1;
        }
    }
}

// ---------------- residual + layernorm (sums the 2 split-K planes + b2) ----------------
__global__ __launch_bounds__(256)
void ln_kernel(const float* __restrict__ g, const float* __restrict__ b,
               const float* __restrict__ b2)
{
    const int row = blockIdx.x;
    const int t = threadIdx.x;
    const int lane = t & 31, w = t >> 5;
    const float x = g_cat[(size_t)row * DMM + t];
    const float y = g_h2[(size_t)row * DMM + t]
                  + g_h2[(size_t)(RTOT + row) * DMM + t]
                  + b2[t] + x;

    __shared__ float s1[8], s2[8];
    __shared__ float s_mu, s_rs;
    float s = y, ss = y * y;
    #pragma unroll
    for (int o = 16; o; o >>= 1) {
        s  += __shfl_down_sync(0xffffffffu, s,  o);
        ss += __shfl_down_sync(0xffffffffu, ss, o);
    }
    if (lane == 0) { s1[w] = s; s2[w] = ss; }
    __syncthreads();
    if (t == 0) {
        float S = 0.f, SS = 0.f;
        #pragma unroll
        for (int i = 0; i < 8; i++) { S += s1[i]; SS += s2[i]; }
        const float mu = S / DMM;
        const float var = SS / DMM - mu * mu;
        s_mu = mu; s_rs = rsqrtf(var + 1e-5f);
    }
    __syncthreads();
    const float o = g[t] * (y - s_mu) * s_rs + b[t];
    if (row < NQ) g_qg[(size_t)row * DMM + t] = o;
    else          g_sse[(size_t)(row - NQ) * DMM + t] = o;
}

// ---------------- support mean + l2norm ----------------
__global__ __launch_bounds__(256)
void support_reduce()
{
    const int t = threadIdx.x;
    const int lane = t & 31, w = t >> 5;
    float s = 0.f;
    #pragma unroll
    for (int r = 0; r < FEWS; r++) s += g_sse[r * DMM + t];
    s *= (1.f / FEWS);
    g_sg[t] = s;

    __shared__ float s1[8];
    __shared__ float s_n;
    float p = s * s;
    #pragma unroll
    for (int o = 16; o; o >>= 1) p += __shfl_down_sync(0xffffffffu, p, o);
    if (lane == 0) s1[w] = p;
    __syncthreads();
    if (t == 0) {
        float S = 0.f;
        #pragma unroll
        for (int i = 0; i < 8; i++) S += s1[i];
        s_n = fmaxf(sqrtf(S), 1e-12f);
    }
    __syncthreads();
    g_sgn[t] = s / s_n;
}

// ---------------- LSTM step 0 on compacted gates ----------------
__global__ __launch_bounds__(256)
void e0_kernel()
{
    const int idx = blockIdx.x * 256 + threadIdx.x;   // NQ*256
    const int row = idx >> 8, j = idx & 255;
    const float* gr = g_GxC + (size_t)row * GC;
    const float ig = 1.f / (1.f + expf(-gr[j]));
    const float gg = tanhf(gr[512 + j]);
    const float c  = ig * gg;
    g_c0[idx] = c;
    const float og = 1.f / (1.f + expf(-gr[768 + j]));
    g_hr[idx] = g_qg[idx] + og * tanhf(c);
}

// ---------------- LSTM step 1 + l2norm + final dot ----------------
__global__ __launch_bounds__(256)
void final_kernel(float* __restrict__ out)
{
    const int row = blockIdx.x;
    const int t = threadIdx.x;
    const int lane = t & 31, w = t >> 5;
    const float* gr = g_gates + (size_t)row * GC;
    const float ig = 1.f / (1.f + expf(-gr[t]));
    const float fg = 1.f / (1.f + expf(-gr[256 + t]));
    const float gg = tanhf(gr[512 + t]);
    const float og = 1.f / (1.f + expf(-gr[768 + t]));
    const float c  = fg * g_c0[(size_t)row * DMM + t] + ig * gg;
    const float h  = g_qg[(size_t)row * DMM + t] + og * tanhf(c);

    float d = h * g_sgn[t];
    float n2 = h * h;
    __shared__ float sd[8], sn[8];
    #pragma unroll
    for (int o = 16; o; o >>= 1) {
        d  += __shfl_down_sync(0xffffffffu, d,  o);
        n2 += __shfl_down_sync(0xffffffffu, n2, o);
    }
    if (lane == 0) { sd[w] = d; sn[w] = n2; }
    __syncthreads();
    if (t == 0) {
        float DT = 0.f, NT = 0.f;
        #pragma unroll
        for (int i = 0; i < 8; i++) { DT += sd[i]; NT += sn[i]; }
        out[row] = DT / fmaxf(sqrtf(NT), 1e-12f);
    }
}

// ---------------- launch ----------------
extern "C" void kernel_launch(void* const* d_in, const int* in_sizes, int n_in,
                              void* d_out, int out_size)
{
    const int*   query   = (const int*)  d_in[0];
    const int*   support = (const int*)  d_in[1];
    const int*   qlc     = (const int*)  d_in[2];
    const int*   qrc     = (const int*)  d_in[4];
    const int*   slc     = (const int*)  d_in[6];
    const int*   src     = (const int*)  d_in[8];
    const float* emb     = (const float*)d_in[10];
    const float* gcnW    = (const float*)d_in[11];
    const float* gbias   = (const float*)d_in[12];
    const float* gb      = (const float*)d_in[13];
    const float* w1      = (const float*)d_in[14];
    const float* b1      = (const float*)d_in[15];
    const float* w2      = (const float*)d_in[16];
    const float* b2      = (const float*)d_in[17];
    const float* lng     = (const float*)d_in[18];
    const float* lnb     = (const float*)d_in[19];
    const float* Wih     = (const float*)d_in[20];
    const float* Whh     = (const float*)d_in[21];
    const float* bih     = (const float*)d_in[22];
    const float* bhh     = (const float*)d_in[23];
    float* out = (float*)d_out;

    float *p_mcat, *p_cat, *p_h1, *p_h2, *p_qg, *p_WihC, *p_WhhC, *p_bsumC, *p_svec;
    float *p_GxC, *p_gates, *p_hr;
    cudaGetSymbolAddress((void**)&p_mcat,  g_mcat);
    cudaGetSymbolAddress((void**)&p_cat,   g_cat);
    cudaGetSymbolAddress((void**)&p_h1,    g_h1);
    cudaGetSymbolAddress((void**)&p_h2,    g_h2);
    cudaGetSymbolAddress((void**)&p_qg,    g_qg);
    cudaGetSymbolAddress((void**)&p_WihC,  g_WihC);
    cudaGetSymbolAddress((void**)&p_WhhC,  g_WhhC);
    cudaGetSymbolAddress((void**)&p_bsumC, g_bsumC);
    cudaGetSymbolAddress((void**)&p_svec,  g_svec);
    cudaGetSymbolAddress((void**)&p_GxC,   g_GxC);
    cudaGetSymbolAddress((void**)&p_gates, g_gates);
    cudaGetSymbolAddress((void**)&p_hr,    g_hr);

    compact_kernel<<<GC * DMM / 256, 256>>>(Wih, Whh, bih, bhh);
    neighbor_all<<<NBLK, 256>>>(emb, qlc, qrc, slc, src, query, support);

    // gcn projection: g_cat = tanh(mcat @ gcnW^T + gbias + gb), scattered layout
    tgemm<4><<<dim3(DD / 64, (NBLK + 63) / 64), 256>>>(p_mcat, gcnW, nullptr, NBLK, DD, DMM, gbias, gb);

    // support encoder (batched query + support rows) — tf32
    tgemm<1><<<dim3(DFF / 64, (RTOT + 63) / 64), 256>>>(p_cat, w1, p_h1, RTOT, DFF, DMM, b1, nullptr);
    tgemm<3><<<dim3(DMM / 64, (RTOT + 63) / 64, 2), 256>>>(p_h1, w2, p_h2, RTOT, DMM, DFF, nullptr, nullptr);
    ln_kernel<<<RTOT, 256>>>(lng, lnb, b2);
    support_reduce<<<1, 256>>>();
    svec_kernel<<<GC / 8, 256>>>(Whh);

    // query encoder on compacted gate columns — tf32
    tgemm<0><<<dim3(GC / 64, NQ / 64), 256>>>(p_qg, p_WihC, p_GxC, NQ, GC, DMM, p_bsumC, nullptr);
    e0_kernel<<<NQ * DMM / 256, 256>>>();
    tgemm<2><<<dim3(GC / 64, NQ / 64), 256>>>(p_hr, p_WhhC, p_gates, NQ, GC, DMM, p_svec, p_GxC);
    final_kernel<<<NQ, 256>>>(out);
}

// round 8
// speedup vs baseline: 3.8000x; 1.0447x over previous
#include <cuda_runtime.h>
#include <math.h>
#include <stdint.h>

#define NQ    1024
#define FEWS  5
#define MCAND 200
#define KSEL  32
#define DD    128
#define DMM   256
#define DFF   512
#define HHH   512
#define GC    1024            // compacted gate columns, interleaved (j*4 + gate)
#define RTOT  (NQ + FEWS)     // 1029
#define NBLK  (2*NQ + 2*FEWS) // 2058 neighbor tasks

// ---------------- workspace (device globals; no allocations) ----------------
__device__ float g_mcat [NBLK * DMM];       // per-task K-mean [rel;ent]
__device__ float g_cat  [RTOT * DMM];
__device__ float g_h1   [RTOT * DFF];
__device__ float g_h2   [2 * RTOT * DMM];   // 2 split-K planes
__device__ float g_qg   [NQ   * DMM];
__device__ float g_sse  [FEWS * DMM];
__device__ float g_sgn  [DMM];
__device__ float g_WihC [GC * DMM];
__device__ float g_WhhC [GC * DMM];
__device__ float g_bsumC[GC];
__device__ float g_svec [GC];
__device__ float g_GxC  [NQ * GC];
__device__ float g_gates[NQ * GC];
__device__ float g_c0   [NQ * DMM];
__device__ float g_hr   [NQ * DMM];

// interleaved gate col r -> original 4H row: gate = r&3, j = r>>2, o = gate*512 + j
__device__ __forceinline__ int orig_col(int r) { return (r & 3) * 512 + (r >> 2); }

__device__ __forceinline__ float sigf(float x) { return 1.f / (1.f + expf(-x)); }

__device__ __forceinline__ uint32_t f2tf(float x) {
    uint32_t r;
    asm("cvt.rna.tf32.f32 %0, %1;" : "=r"(r) : "f"(x));
    return r;
}

__device__ __forceinline__ void mma8(float* c, const uint4& a, const uint2& b) {
    asm volatile(
        "mma.sync.aligned.m16n8k8.row.col.f32.tf32.tf32.f32 "
        "{%0,%1,%2,%3}, {%4,%5,%6,%7}, {%8,%9}, {%0,%1,%2,%3};"
        : "+f"(c[0]), "+f"(c[1]), "+f"(c[2]), "+f"(c[3])
        : "r"(a.x), "r"(a.y), "r"(a.z), "r"(a.w), "r"(b.x), "r"(b.y));
}

// ---------------- weight compaction: live gate columns, interleaved ----------------
__global__ __launch_bounds__(256)
void compact_kernel(const float* __restrict__ Wih, const float* __restrict__ Whh,
                    const float* __restrict__ bih, const float* __restrict__ bhh)
{
    const int idx = blockIdx.x * 256 + threadIdx.x;   // GC*DMM threads
    const int r = idx >> 8, c = idx & 255;
    const int o = orig_col(r);
    g_WihC[idx] = Wih[(size_t)o * DMM + c];
    g_WhhC[idx] = Whh[(size_t)o * HHH + c];
    if (c == 0) g_bsumC[r] = bih[o] + bhh[o];
}

// ---------------- svec + support mean + sgn (merged) ----------------
// svec[r] = dot(Whh[orig(r), 256:512], support_g); block 0 also writes sgn.
__global__ __launch_bounds__(256)
void svec_kernel(const float* __restrict__ Whh)
{
    const int t = threadIdx.x;
    const int lane = t & 31, w = t >> 5;
    __shared__ float ssg[DMM];
    __shared__ float s1[8];
    __shared__ float s_n;

    float s = 0.f;
    #pragma unroll
    for (int r = 0; r < FEWS; r++) s += g_sse[r * DMM + t];
    ssg[t] = s * (1.f / FEWS);
    __syncthreads();

    const int r = blockIdx.x * 8 + w;      // grid 128 -> 1024 warps
    const int o = orig_col(r);
    const float* wr = Whh + (size_t)o * HHH + DMM;
    float p = 0.f;
    #pragma unroll
    for (int c = lane; c < DMM; c += 32) p += wr[c] * ssg[c];
    #pragma unroll
    for (int off = 16; off; off >>= 1) p += __shfl_down_sync(0xffffffffu, p, off);
    if (lane == 0) g_svec[r] = p;

    if (blockIdx.x == 0) {
        __syncthreads();
        float q = ssg[t] * ssg[t];
        #pragma unroll
        for (int off = 16; off; off >>= 1) q += __shfl_down_sync(0xffffffffu, q, off);
        if (lane == 0) s1[w] = q;
        __syncthreads();
        if (t == 0) {
            float S = 0.f;
            #pragma unroll
            for (int i = 0; i < 8; i++) S += s1[i];
            s_n = fmaxf(sqrtf(S), 1e-12f);
        }
        __syncthreads();
        g_sgn[t] = ssg[t] / s_n;
    }
}

// ---------------- neighbor encoder: sims + top-K + mean only ----------------
__global__ __launch_bounds__(256)
void neighbor_all(const float* __restrict__ emb,
                  const int* __restrict__ qlc, const int* __restrict__ qrc,
                  const int* __restrict__ slc, const int* __restrict__ src,
                  const int* __restrict__ query, const int* __restrict__ support)
{
    const int b = blockIdx.x;
    const int t = threadIdx.x;
    const int lane = t & 31;
    const int w = t >> 5;

    const int* conn_row;
    int cid, tt;
    if (b < NQ)            { conn_row = qlc + (size_t)b * MCAND * 2;                 cid = query[b * 2 + 0];   tt = b; }
    else if (b < 2 * NQ)   { int rb = b - NQ;        conn_row = qrc + (size_t)rb * MCAND * 2; cid = query[rb * 2 + 1];   tt = RTOT + rb; }
    else if (b < 2*NQ+FEWS){ int rb = b - 2*NQ;      conn_row = slc + (size_t)rb * MCAND * 2; cid = support[rb*2 + 0];   tt = NQ + rb; }
    else                   { int rb = b - 2*NQ-FEWS; conn_row = src + (size_t)rb * MCAND * 2; cid = support[rb*2 + 1];   tt = RTOT + NQ + rb; }

    __shared__ __align__(16) float s_center[DD];
    __shared__ float s_sim [MCAND];
    __shared__ int   s_ridx[MCAND];
    __shared__ int   s_eidx[MCAND];
    __shared__ int   s_selr[KSEL];
    __shared__ int   s_sele[KSEL];
    __shared__ float s_red[8];
    __shared__ float s_cn;

    for (int n = t; n < MCAND; n += 256) {
        s_ridx[n] = conn_row[n * 2 + 0];
        s_eidx[n] = conn_row[n * 2 + 1];
    }
    float cv = 0.f;
    if (t < DD) { cv = emb[(size_t)cid * DD + t]; s_center[t] = cv; }

    float p = cv * cv;
    #pragma unroll
    for (int o = 16; o; o >>= 1) p += __shfl_down_sync(0xffffffffu, p, o);
    if (lane == 0) s_red[w] = p;
    __syncthreads();
    if (t == 0) {
        float s = 0.f;
        #pragma unroll
        for (int i = 0; i < 8; i++) s += s_red[i];
        s_cn = sqrtf(s);
    }
    __syncthreads();
    const float cn = s_cn;

    const float4 c4 = *(const float4*)(s_center + lane * 4);
    for (int n = w; n < MCAND; n += 16) {
        const int n1 = n + 8;
        const bool h1 = n1 < MCAND;
        const float4 e0 = *(const float4*)(emb + (size_t)s_eidx[n] * DD + lane * 4);
        float4 e1 = e0;
        if (h1) e1 = *(const float4*)(emb + (size_t)s_eidx[n1] * DD + lane * 4);
        float num0 = e0.x*c4.x + e0.y*c4.y + e0.z*c4.z + e0.w*c4.w;
        float nn0  = e0.x*e0.x + e0.y*e0.y + e0.z*e0.z + e0.w*e0.w;
        float num1 = e1.x*c4.x + e1.y*c4.y + e1.z*c4.z + e1.w*c4.w;
        float nn1  = e1.x*e1.x + e1.y*e1.y + e1.z*e1.z + e1.w*e1.w;
        #pragma unroll
        for (int o = 16; o; o >>= 1) {
            num0 += __shfl_down_sync(0xffffffffu, num0, o);
            nn0  += __shfl_down_sync(0xffffffffu, nn0,  o);
            num1 += __shfl_down_sync(0xffffffffu, num1, o);
            nn1  += __shfl_down_sync(0xffffffffu, nn1,  o);
        }
        if (lane == 0) {
            s_sim[n] = num0 / fmaxf(cn * sqrtf(nn0), 1e-8f);
            if (h1) s_sim[n1] = num1 / fmaxf(cn * sqrtf(nn1), 1e-8f);
        }
    }
    __syncthreads();

    // top-K with jax.lax.top_k tie-break (lower index wins); rank is a permutation
    if (t < MCAND) {
        const float v = s_sim[t];
        int r = 0;
        for (int i = 0; i < MCAND; i++) {
            const float u = s_sim[i];
            r += (u > v) || (u == v && i < t);
        }
        if (r < KSEL) { s_selr[r] = s_ridx[t]; s_sele[r] = s_eidx[t]; }
    }
    __syncthreads();

    {
        float acc = 0.f;
        if (t < DD) {
            #pragma unroll 8
            for (int k = 0; k < KSEL; k++) acc += emb[(size_t)s_selr[k] * DD + t];
        } else {
            const int d = t - DD;
            #pragma unroll 8
            for (int k = 0; k < KSEL; k++) acc += emb[(size_t)s_sele[k] * DD + d];
        }
        g_mcat[(size_t)tt * DMM + t] = acc * (1.f / KSEL);
    }
}

// ---------------- tf32 tensor-core GEMM: C[M,N] = A[M,K] @ B[N,K]^T ----------------
// Block tile 64x64, BK=32, 8 warps (2m x 4n), warp tile 32x16 via m16n8k8 mma.
// Prefetch distance 2: STORET(kt+1) -> LOADT(kt+2) -> compute(kt) -> sync.
// EPI: 0 = +bias[n], 1 = relu(+bias[n]), 2 = +Cadd[m,n]+bias[n], 3 = raw (split-K),
//      4 = tanh(+bias[n]+Cadd[n]) scattered to g_cat,
//      5 = +bias[n], store C, AND fused LSTM step-0 (c0/hr; Cadd = qg)
template <int EPI>
__global__ __launch_bounds__(256)
void tgemm(const float* __restrict__ A, const float* __restrict__ Bm,
           float* __restrict__ C, int M, int N, int K,
           const float* __restrict__ bias, const float* __restrict__ Cadd)
{
    __shared__ __align__(16) uint32_t As[2][2048];
    __shared__ __align__(16) uint32_t Bs[2][2048];

    const int t    = threadIdx.x;
    const int lane = t & 31;
    const int w    = t >> 5;
    const int wm   = w >> 2;
    const int wn   = w & 3;
    const int m0   = blockIdx.y * 64;
    const int n0   = blockIdx.x * 64;
    const int ksz  = K / gridDim.z;
    const int kb   = blockIdx.z * ksz;

    const int srow = t >> 3;
    const int k4   = t & 7;
    const int ks_s = k4 >> 1;
    const int jA   = (k4 & 1) * 2;
    const int jB   = (k4 & 1);

    float acc[2][2][4];
    #pragma unroll
    for (int i = 0; i < 2; i++)
        #pragma unroll
        for (int j = 0; j < 2; j++)
            #pragma unroll
            for (int q = 0; q < 4; q++) acc[i][j][q] = 0.f;

    const float4 z4 = make_float4(0.f, 0.f, 0.f, 0.f);
    float4 ga[2], gb[2];

    #define TLOAD(kt)                                                          \
        { _Pragma("unroll")                                                    \
          for (int p = 0; p < 2; p++) {                                        \
            const int rr = p * 32 + srow;                                      \
            const int m = m0 + rr;                                             \
            ga[p] = (m < M) ? *(const float4*)(A + (size_t)m * K + kb + (kt)*32 + k4*4) : z4; \
            gb[p] = *(const float4*)(Bm + (size_t)(n0 + rr) * K + kb + (kt)*32 + k4*4);       \
          } }

    #define TSTORE(buf)                                                        \
        { _Pragma("unroll")                                                    \
          for (int p = 0; p < 2; p++) {                                        \
            const int rr = p * 32 + srow;                                      \
            const int mt = rr >> 4, rr16 = rr & 15;                            \
            const int lbA = (rr16 & 7) * 4;                                    \
            const int jjA = (rr16 >> 3) + jA;                                  \
            uint32_t* da = &As[buf][(mt*4 + ks_s)*128 + jjA];                  \
            da[(lbA+0)*4] = f2tf(ga[p].x); da[(lbA+1)*4] = f2tf(ga[p].y);      \
            da[(lbA+2)*4] = f2tf(ga[p].z); da[(lbA+3)*4] = f2tf(ga[p].w);      \
            const int nt = rr >> 3, nn8 = rr & 7;                              \
            uint32_t* db = &Bs[buf][(nt*4 + ks_s)*64 + jB];                    \
            db[(nn8*4+0)*2] = f2tf(gb[p].x); db[(nn8*4+1)*2] = f2tf(gb[p].y);  \
            db[(nn8*4+2)*2] = f2tf(gb[p].z); db[(nn8*4+3)*2] = f2tf(gb[p].w);  \
          } }

    const int nkt = ksz >> 5;
    TLOAD(0);
    TSTORE(0);
    if (nkt > 1) TLOAD(1);
    __syncthreads();

    for (int kt = 0; kt < nkt; kt++) {
        const int cur = kt & 1;
        if (kt + 1 < nkt) TSTORE(cur ^ 1);     // regs hold kt+1; buffer consumed in kt-1
        if (kt + 2 < nkt) TLOAD(kt + 2);       // full ktile to cover LDG latency
        #pragma unroll
        for (int ks = 0; ks < 4; ks++) {
            uint4 afr[2];
            uint2 bfr[2];
            #pragma unroll
            for (int i = 0; i < 2; i++)
                afr[i] = *(const uint4*)&As[cur][((wm*2 + i)*4 + ks)*128 + lane*4];
            #pragma unroll
            for (int j = 0; j < 2; j++)
                bfr[j] = *(const uint2*)&Bs[cur][((wn*2 + j)*4 + ks)*64 + lane*2];
            #pragma unroll
            for (int i = 0; i < 2; i++)
                #pragma unroll
                for (int j = 0; j < 2; j++)
                    mma8(acc[i][j], afr[i], bfr[j]);
        }
        if (kt + 1 < nkt) __syncthreads();
    }
    #undef TLOAD
    #undef TSTORE

    C += (size_t)blockIdx.z * M * N;
    const int mr  = lane >> 2;
    const int nc  = (lane & 3) * 2;
    #pragma unroll
    for (int i = 0; i < 2; i++) {
        #pragma unroll
        for (int j = 0; j < 2; j++) {
            const int mrow = m0 + wm*32 + i*16 + mr;
            const int ncol = n0 + wn*16 + j*8 + nc;
            if (EPI == 4) {
                const float2 bb = *(const float2*)(bias + ncol);
                const float2 cc = *(const float2*)(Cadd + ncol);
                #pragma unroll
                for (int q = 0; q < 2; q++) {
                    const int mm = mrow + q * 8;
                    if (mm < M) {
                        const int r    = (mm < RTOT) ? mm : mm - RTOT;
                        const int coff = (mm < RTOT) ? 0 : DD;
                        float2 v;
                        v.x = tanhf(acc[i][j][q*2+0] + bb.x + cc.x);
                        v.y = tanhf(acc[i][j][q*2+1] + bb.y + cc.y);
                        *(float2*)(g_cat + (size_t)r * DMM + coff + ncol) = v;
                    }
                }
                continue;
            }
            float2 bv = make_float2(0.f, 0.f);
            if (EPI != 3) bv = *(const float2*)(bias + ncol);
            float2 v0 = make_float2(acc[i][j][0] + bv.x, acc[i][j][1] + bv.y);
            float2 v1 = make_float2(acc[i][j][2] + bv.x, acc[i][j][3] + bv.y);
            if (EPI == 5) {
                // store Gx
                if (mrow < M)     *(float2*)(C + (size_t)mrow * N + ncol) = v0;
                if (mrow + 8 < M) *(float2*)(C + (size_t)(mrow + 8) * N + ncol) = v1;
                // gate exchange: even lane-pair member has (i,f), odd has (g,o), same j
                const float rx0 = __shfl_xor_sync(0xffffffffu, v0.x, 1);
                const float ry0 = __shfl_xor_sync(0xffffffffu, v0.y, 1);
                const float rx1 = __shfl_xor_sync(0xffffffffu, v1.x, 1);
                const float ry1 = __shfl_xor_sync(0xffffffffu, v1.y, 1);
                (void)ry1;
                const int jj = ncol >> 2;
                int myrow; float gi, gg, go;
                if ((lane & 1) == 0) { myrow = mrow;     gi = v0.x; gg = rx0;  go = ry0;  }
                else                 { myrow = mrow + 8; gi = rx1;  gg = v1.x; go = v1.y; }
                if (myrow < M) {
                    const float c0 = sigf(gi) * tanhf(gg);
                    const float h  = Cadd[(size_t)myrow * DMM + jj] + sigf(go) * tanhf(c0);
                    g_c0[(size_t)myrow * DMM + jj] = c0;
                    g_hr[(size_t)myrow * DMM + jj] = h;
                }
                continue;
            }
            if (EPI == 1) {
                v0.x = fmaxf(v0.x, 0.f); v0.y = fmaxf(v0.y, 0.f);
                v1.x = fmaxf(v1.x, 0.f); v1.y = fmaxf(v1.y, 0.f);
            }
            if (EPI == 2) {
                if (mrow < M) {
                    float2 c0 = *(const float2*)(Cadd + (size_t)mrow * N + ncol);
                    v0.x += c0.x; v0.y += c0.y;
                }
                if (mrow + 8 < M) {
                    float2 c1 = *(const float2*)(Cadd + (size_t)(mrow + 8) * N + ncol);
                    v1.x += c1.x; v1.y += c1.y;
                }
            }
            if (mrow < M)     *(float2*)(C + (size_t)mrow * N + ncol) = v0;
            if (mrow + 8 < M) *(float2*)(C + (size_t)(mrow + 8) * N + ncol) = v1;
        }
    }
}

// ---------------- residual + layernorm (sums the 2 split-K planes + b2) ----------------
__global__ __launch_bounds__(256)
void ln_kernel(const float* __restrict__ g, const float* __restrict__ b,
               const float* __restrict__ b2)
{
    const int row = blockIdx.x;
    const int t = threadIdx.x;
    const int lane = t & 31, w = t >> 5;
    const float x = g_cat[(size_t)row * DMM + t];
    const float y = g_h2[(size_t)row * DMM + t]
                  + g_h2[(size_t)(RTOT + row) * DMM + t]
                  + b2[t] + x;

    __shared__ float s1[8], s2[8];
    __shared__ float s_mu, s_rs;
    float s = y, ss = y * y;
    #pragma unroll
    for (int o = 16; o; o >>= 1) {
        s  += __shfl_down_sync(0xffffffffu, s,  o);
        ss += __shfl_down_sync(0xffffffffu, ss, o);
    }
    if (lane == 0) { s1[w] = s; s2[w] = ss; }
    __syncthreads();
    if (t == 0) {
        float S = 0.f, SS = 0.f;
        #pragma unroll
        for (int i = 0; i < 8; i++) { S += s1[i]; SS += s2[i]; }
        const float mu = S / DMM;
        const float var = SS / DMM - mu * mu;
        s_mu = mu; s_rs = rsqrtf(var + 1e-5f);
    }
    __syncthreads();
    const float o = g[t] * (y - s_mu) * s_rs + b[t];
    if (row < NQ) g_qg[(size_t)row * DMM + t] = o;
    else          g_sse[(size_t)(row - NQ) * DMM + t] = o;
}

// ---------------- LSTM step 1 + l2norm + final dot (interleaved gates) ----------------
__global__ __launch_bounds__(256)
void final_kernel(float* __restrict__ out)
{
    const int row = blockIdx.x;
    const int t = threadIdx.x;
    const int lane = t & 31, w = t >> 5;
    const float4 g4 = *(const float4*)(g_gates + (size_t)row * GC + t * 4);
    const float ig = sigf(g4.x);
    const float fg = sigf(g4.y);
    const float gg = tanhf(g4.z);
    const float og = sigf(g4.w);
    const float c  = fg * g_c0[(size_t)row * DMM + t] + ig * gg;
    const float h  = g_qg[(size_t)row * DMM + t] + og * tanhf(c);

    float d = h * g_sgn[t];
    float n2 = h * h;
    __shared__ float sd[8], sn[8];
    #pragma unroll
    for (int o = 16; o; o >>= 1) {
        d  += __shfl_down_sync(0xffffffffu, d,  o);
        n2 += __shfl_down_sync(0xffffffffu, n2, o);
    }
    if (lane == 0) { sd[w] = d; sn[w] = n2; }
    __syncthreads();
    if (t == 0) {
        float DT = 0.f, NT = 0.f;
        #pragma unroll
        for (int i = 0; i < 8; i++) { DT += sd[i]; NT += sn[i]; }
        out[row] = DT / fmaxf(sqrtf(NT), 1e-12f);
    }
}

// ---------------- launch ----------------
extern "C" void kernel_launch(void* const* d_in, const int* in_sizes, int n_in,
                              void* d_out, int out_size)
{
    const int*   query   = (const int*)  d_in[0];
    const int*   support = (const int*)  d_in[1];
    const int*   qlc     = (const int*)  d_in[2];
    const int*   qrc     = (const int*)  d_in[4];
    const int*   slc     = (const int*)  d_in[6];
    const int*   src     = (const int*)  d_in[8];
    const float* emb     = (const float*)d_in[10];
    const float* gcnW    = (const float*)d_in[11];
    const float* gbias   = (const float*)d_in[12];
    const float* gb      = (const float*)d_in[13];
    const float* w1      = (const float*)d_in[14];
    const float* b1      = (const float*)d_in[15];
    const float* w2      = (const float*)d_in[16];
    const float* b2      = (const float*)d_in[17];
    const float* lng     = (const float*)d_in[18];
    const float* lnb     = (const float*)d_in[19];
    const float* Wih     = (const float*)d_in[20];
    const float* Whh     = (const float*)d_in[21];
    const float* bih     = (const float*)d_in[22];
    const float* bhh     = (const float*)d_in[23];
    float* out = (float*)d_out;

    float *p_mcat, *p_cat, *p_h1, *p_h2, *p_qg, *p_WihC, *p_WhhC, *p_bsumC, *p_svec;
    float *p_GxC, *p_gates, *p_hr;
    cudaGetSymbolAddress((void**)&p_mcat,  g_mcat);
    cudaGetSymbolAddress((void**)&p_cat,   g_cat);
    cudaGetSymbolAddress((void**)&p_h1,    g_h1);
    cudaGetSymbolAddress((void**)&p_h2,    g_h2);
    cudaGetSymbolAddress((void**)&p_qg,    g_qg);
    cudaGetSymbolAddress((void**)&p_WihC,  g_WihC);
    cudaGetSymbolAddress((void**)&p_WhhC,  g_WhhC);
    cudaGetSymbolAddress((void**)&p_bsumC, g_bsumC);
    cudaGetSymbolAddress((void**)&p_svec,  g_svec);
    cudaGetSymbolAddress((void**)&p_GxC,   g_GxC);
    cudaGetSymbolAddress((void**)&p_gates, g_gates);
    cudaGetSymbolAddress((void**)&p_hr,    g_hr);

    compact_kernel<<<GC * DMM / 256, 256>>>(Wih, Whh, bih, bhh);
    neighbor_all<<<NBLK, 256>>>(emb, qlc, qrc, slc, src, query, support);

    // gcn projection: g_cat = tanh(mcat @ gcnW^T + gbias + gb), scattered layout
    tgemm<4><<<dim3(DD / 64, (NBLK + 63) / 64), 256>>>(p_mcat, gcnW, nullptr, NBLK, DD, DMM, gbias, gb);

    // support encoder (batched query + support rows)
    tgemm<1><<<dim3(DFF / 64, (RTOT + 63) / 64), 256>>>(p_cat, w1, p_h1, RTOT, DFF, DMM, b1, nullptr);
    tgemm<3><<<dim3(DMM / 64, (RTOT + 63) / 64, 2), 256>>>(p_h1, w2, p_h2, RTOT, DMM, DFF, nullptr, nullptr);
    ln_kernel<<<RTOT, 256>>>(lng, lnb, b2);
    svec_kernel<<<GC / 8, 256>>>(Whh);

    // query encoder: Gx GEMM with fused LSTM step-0 (EPI 5, Cadd = qg)
    tgemm<5><<<dim3(GC / 64, NQ / 64), 256>>>(p_qg, p_WihC, p_GxC, NQ, GC, DMM, p_bsumC, p_qg);
    tgemm<2><<<dim3(GC / 64, NQ / 64), 256>>>(p_hr, p_WhhC, p_gates, NQ, GC, DMM, p_svec, p_GxC);
    final_kernel<<<NQ, 256>>>(out);
}